// round 9
// baseline (speedup 1.0000x reference)
#include <cuda_runtime.h>
#include <cuda_fp16.h>
#include <stdint.h>

// ---------------- scratch (alloc-free: __device__ globals) ----------------
__device__ __half g_S [16u * 1024u * 2048u];   // logits / probs  [B,NQ,NK]  fp16
__device__ __half g_Vt[16u * 256u  * 2048u];   // V'^T = W @ V^T  [B,O,NK]   fp16
__device__ __half g_Qh[16u * 1024u * 512u];    // queries fp16
__device__ __half g_Kh[16u * 2048u * 512u];    // keys fp16

#define MASKV (-60000.0f)   // fp16-representable "minus infinity"

// ---------------- helpers ----------------
__device__ __forceinline__ uint32_t smem_u32(const void* p) {
    uint32_t a;
    asm("{ .reg .u64 t; cvta.to.shared.u64 t, %1; cvt.u32.u64 %0, t; }" : "=r"(a) : "l"(p));
    return a;
}
__device__ __forceinline__ uint32_t f16x2(float lo, float hi) {
    uint32_t u;
    asm("cvt.rn.f16x2.f32 %0, %1, %2;" : "=r"(u) : "f"(hi), "f"(lo));
    return u;
}
__device__ __forceinline__ void mma_f16(float c[4], const uint32_t a[4], const uint32_t b[2]) {
    asm volatile(
        "mma.sync.aligned.m16n8k16.row.col.f32.f16.f16.f32 "
        "{%0,%1,%2,%3}, {%4,%5,%6,%7}, {%8,%9}, {%0,%1,%2,%3};"
        : "+f"(c[0]), "+f"(c[1]), "+f"(c[2]), "+f"(c[3])
        : "r"(a[0]), "r"(a[1]), "r"(a[2]), "r"(a[3]), "r"(b[0]), "r"(b[1]));
}
__device__ __forceinline__ void ldsm4(uint32_t& r0, uint32_t& r1, uint32_t& r2, uint32_t& r3,
                                      uint32_t addr) {
    asm volatile("ldmatrix.sync.aligned.m8n8.x4.shared.b16 {%0,%1,%2,%3}, [%4];"
                 : "=r"(r0), "=r"(r1), "=r"(r2), "=r"(r3) : "r"(addr));
}
__device__ __forceinline__ void sts64(uint32_t a, uint32_t x, uint32_t y) {
    asm volatile("st.shared.v2.b32 [%0], {%1,%2};" :: "r"(a), "r"(x), "r"(y) : "memory");
}
__device__ __forceinline__ void cpasync16(uint32_t dst, const void* src) {
    asm volatile("cp.async.cg.shared.global [%0], [%1], 16;" :: "r"(dst), "l"(src) : "memory");
}
#define CP_COMMIT() asm volatile("cp.async.commit_group;" ::: "memory")
#define CP_WAIT2()  asm volatile("cp.async.wait_group 2;" ::: "memory")

// ---------------- tiling ----------------
// fp16 smem rows: 64B data, stride 80B (conflict-free ldmatrix).
constexpr int BM = 128, BN = 128, BK = 32;
constexpr int SBH   = 80;                   // bytes per smem row
constexpr int A_B   = BM * SBH;             // 10240
constexpr int STG_B = (BM + BN) * SBH;      // 20480 per stage
constexpr int NSTG  = 4;
constexpr int SMEM_CP = NSTG * STG_B;       // 81920 (cp.async kernels)
constexpr int SMEM_DB = 2 * STG_B;          // 40960 (fp32-input kernel)

// ===================== fp32 -> fp16 convert (grid-stride) ==================
__global__ __launch_bounds__(256)
void cvt_f2h(const float4* __restrict__ src, uint2* __restrict__ dst, int n4)
{
    for (int i = blockIdx.x * 256 + threadIdx.x; i < n4; i += gridDim.x * 256) {
        float4 v = src[i];
        uint2 o;
        o.x = f16x2(v.x, v.y);
        o.y = f16x2(v.z, v.w);
        dst[i] = o;
    }
}

// ===================== GEMM: fp16 in, cp.async, 256 thr, 8 warps ===========
// CTA tile 128x128x32; warps 2(M) x 4(N), warp tile 64x32. 2 CTAs/SM ->
// 16 warps/SM (4 per SMSP) to hide ldsm/barrier/cp latency.
// EPI 1: scale + mask -> MASKV, fp16 out (K1).   EPI 2: +bias, fp32 out (K3).
template <int EPI>
__global__ __launch_bounds__(256, 2)
void gemm_cp(const __half* __restrict__ Ag, const __half* __restrict__ Bg,
             void* __restrict__ Cg, int N, int K,
             long long sA, long long sB, long long sC,
             const int* __restrict__ maskg, long long sMask,
             const float* __restrict__ bias, float scale)
{
    extern __shared__ char smem[];

    const int tid  = threadIdx.x;
    const int lane = tid & 31;
    const int warp = tid >> 5;
    const int wm = (warp & 1) * 64;        // 2 warps along M
    const int wn = (warp >> 1) * 32;       // 4 warps along N, 32 cols each
    const int z  = blockIdx.z;
    const int m0 = blockIdx.y * BM;
    const int n0 = blockIdx.x * BN;

    const __half* A = Ag + (size_t)z * sA;
    const __half* B = Bg + (size_t)z * sB;

    const uint32_t sbase = smem_u32(smem);
    const uint32_t aRowB = (uint32_t)(wm + (lane & 15)) * SBH + (uint32_t)(lane >> 4) * 16;
    const uint32_t bRowB = (uint32_t)(wn + (lane & 7) + ((lane >> 4) << 3)) * SBH
                         + (uint32_t)((lane >> 3) & 1) * 16;
    const int KT = K / BK;

    // one chunk = 4 cp.async x 16B per thread (A 2, B 2)
    const int r4 = tid >> 2;               // 0..63 base row
    const int sg = (tid & 3) * 16;         // 16B segment within 64B row
    auto issue_chunk = [&](int c) {
        const uint32_t st = sbase + (uint32_t)(c & (NSTG - 1)) * STG_B;
        const int koff = c * BK + (tid & 3) * 8;
#pragma unroll
        for (int i = 0; i < 2; i++) {
            int r = r4 + 64 * i;
            cpasync16(st + (uint32_t)r * SBH + sg, A + (size_t)(m0 + r) * K + koff);
        }
#pragma unroll
        for (int i = 0; i < 2; i++) {
            int r = r4 + 64 * i;
            cpasync16(st + (uint32_t)A_B + (uint32_t)r * SBH + sg,
                      B + (size_t)(n0 + r) * K + koff);
        }
    };

    float acc[4][4][4];
#pragma unroll
    for (int i = 0; i < 4; i++)
#pragma unroll
        for (int j = 0; j < 4; j++)
#pragma unroll
            for (int r = 0; r < 4; r++) acc[i][j][r] = 0.0f;

    issue_chunk(0); CP_COMMIT();
    issue_chunk(1); CP_COMMIT();
    issue_chunk(2); CP_COMMIT();

    for (int kb = 0; kb < KT; ++kb) {
        CP_WAIT2();                 // chunk kb landed (thread-local)
        __syncthreads();            // visible to all; stage (kb+3)&3 free
        if (kb + 3 < KT) issue_chunk(kb + 3);
        CP_COMMIT();

        const uint32_t curBase = sbase + (uint32_t)(kb & (NSTG - 1)) * STG_B;
        const uint32_t aB = curBase + aRowB;
        const uint32_t bB = curBase + (uint32_t)A_B + bRowB;

#pragma unroll
        for (int ks = 0; ks < 2; ++ks) {            // 2 x K=16 per chunk
            const uint32_t kB = (uint32_t)ks * 32;
            uint32_t af[4][4], bf[4][2];
#pragma unroll
            for (int mi = 0; mi < 4; mi++)
                ldsm4(af[mi][0], af[mi][1], af[mi][2], af[mi][3],
                      aB + (uint32_t)mi * (16 * SBH) + kB);
#pragma unroll
            for (int pr = 0; pr < 2; pr++)
                ldsm4(bf[2 * pr][0], bf[2 * pr][1], bf[2 * pr + 1][0], bf[2 * pr + 1][1],
                      bB + (uint32_t)pr * (16 * SBH) + kB);
#pragma unroll
            for (int mi = 0; mi < 4; mi++)
#pragma unroll
                for (int ni = 0; ni < 4; ni++)
                    mma_f16(acc[mi][ni], af[mi], bf[ni]);
        }
        __syncthreads();
    }

    // ---------------- epilogue ----------------
#pragma unroll
    for (int mi = 0; mi < 4; mi++) {
#pragma unroll
        for (int ni = 0; ni < 4; ni++) {
            const int row0 = m0 + wm + mi * 16 + (lane >> 2);
            const int col  = n0 + wn + ni * 8 + (lane & 3) * 2;
#pragma unroll
            for (int h = 0; h < 2; ++h) {
                const int row = row0 + h * 8;
                float v0 = acc[mi][ni][2 * h];
                float v1 = acc[mi][ni][2 * h + 1];
                if (EPI == 1) {
                    __half* C = (__half*)Cg + (size_t)z * sC;
                    const int* Mk = maskg + (size_t)z * sMask;
                    v0 *= scale; v1 *= scale;
                    int2 mk = *(const int2*)(Mk + (size_t)row * N + col);
                    if (mk.x == 0) v0 = MASKV;
                    if (mk.y == 0) v1 = MASKV;
                    *(__half2*)(C + (size_t)row * N + col) = __floats2half2_rn(v0, v1);
                } else {
                    float* C = (float*)Cg + (size_t)z * sC;
                    float2 o;
                    o.x = v0 + bias[col];
                    o.y = v1 + bias[col + 1];
                    *(float2*)(C + (size_t)row * N + col) = o;
                }
            }
        }
    }
}

// ===================== GEMM: fp32 inputs -> fp16 out (K0 only) =============
// 128 threads, 4 warps 2x2, warp tile 64x64 (unchanged from R7 — works well).
__global__ __launch_bounds__(128, 2)
void gemm_a32(const float* __restrict__ Ag, const float* __restrict__ Bg,
              __half* __restrict__ Cg, int N, int K,
              long long sA, long long sB, long long sC)
{
    extern __shared__ char smem[];

    const int tid  = threadIdx.x;
    const int lane = tid & 31;
    const int warp = tid >> 5;
    const int wm = (warp & 1) * 64;
    const int wn = (warp >> 1) * 64;
    const int z  = blockIdx.z;
    const int m0 = blockIdx.y * BM;
    const int n0 = blockIdx.x * BN;

    const float* A = Ag + (size_t)z * sA;
    const float* B = Bg + (size_t)z * sB;

    const uint32_t sbase = smem_u32(smem);
    const uint32_t aRowB = (uint32_t)(wm + (lane & 15)) * SBH + (uint32_t)(lane >> 4) * 16;
    const uint32_t bRowB = (uint32_t)(wn + (lane & 7) + ((lane >> 4) << 3)) * SBH
                         + (uint32_t)((lane >> 3) & 1) * 16;
    const int KT = K / BK;

    float4 ra[8], rb[8];
    auto load_regs = [&](int c) {
        const int koff = c * BK;
#pragma unroll
        for (int i = 0; i < 8; i++) {
            int f = tid + 128 * i, r = f >> 3, q = (f & 7) * 4;
            ra[i] = *(const float4*)(A + (size_t)(m0 + r) * K + koff + q);
        }
#pragma unroll
        for (int i = 0; i < 8; i++) {
            int f = tid + 128 * i, r = f >> 3, q = (f & 7) * 4;
            rb[i] = *(const float4*)(B + (size_t)(n0 + r) * K + koff + q);
        }
    };
    auto store_stage = [&](int s) {
        const uint32_t st = sbase + (uint32_t)s * STG_B;
#pragma unroll
        for (int i = 0; i < 8; i++) {
            int f = tid + 128 * i, r = f >> 3, q = (f & 7) * 4;
            sts64(st + (uint32_t)r * SBH + (uint32_t)q * 2,
                  f16x2(ra[i].x, ra[i].y), f16x2(ra[i].z, ra[i].w));
        }
#pragma unroll
        for (int i = 0; i < 8; i++) {
            int f = tid + 128 * i, r = f >> 3, q = (f & 7) * 4;
            sts64(st + (uint32_t)A_B + (uint32_t)r * SBH + (uint32_t)q * 2,
                  f16x2(rb[i].x, rb[i].y), f16x2(rb[i].z, rb[i].w));
        }
    };

    float acc[4][8][4];
#pragma unroll
    for (int i = 0; i < 4; i++)
#pragma unroll
        for (int j = 0; j < 8; j++)
#pragma unroll
            for (int r = 0; r < 4; r++) acc[i][j][r] = 0.0f;

    load_regs(0);
    store_stage(0);
    __syncthreads();
    if (KT > 1) load_regs(1);

    for (int kb = 0; kb < KT; ++kb) {
        const int cur = kb & 1;
        if (kb + 1 < KT) store_stage(cur ^ 1);
        if (kb + 2 < KT) load_regs(kb + 2);

        const uint32_t curBase = sbase + (uint32_t)cur * STG_B;
        const uint32_t aB = curBase + aRowB;
        const uint32_t bB = curBase + (uint32_t)A_B + bRowB;

#pragma unroll
        for (int ks = 0; ks < 2; ++ks) {
            const uint32_t kB = (uint32_t)ks * 32;
            uint32_t af[4][4], bf[8][2];
#pragma unroll
            for (int mi = 0; mi < 4; mi++)
                ldsm4(af[mi][0], af[mi][1], af[mi][2], af[mi][3],
                      aB + (uint32_t)mi * (16 * SBH) + kB);
#pragma unroll
            for (int pr = 0; pr < 4; pr++)
                ldsm4(bf[2 * pr][0], bf[2 * pr][1], bf[2 * pr + 1][0], bf[2 * pr + 1][1],
                      bB + (uint32_t)pr * (16 * SBH) + kB);
#pragma unroll
            for (int mi = 0; mi < 4; mi++)
#pragma unroll
                for (int ni = 0; ni < 8; ni++)
                    mma_f16(acc[mi][ni], af[mi], bf[ni]);
        }
        __syncthreads();
    }

    __half* C = Cg + (size_t)z * sC;
#pragma unroll
    for (int mi = 0; mi < 4; mi++) {
#pragma unroll
        for (int ni = 0; ni < 8; ni++) {
            const int row0 = m0 + wm + mi * 16 + (lane >> 2);
            const int col  = n0 + wn + ni * 8 + (lane & 3) * 2;
#pragma unroll
            for (int h = 0; h < 2; ++h) {
                const int row = row0 + h * 8;
                *(__half2*)(C + (size_t)row * N + col) =
                    __floats2half2_rn(acc[mi][ni][2 * h], acc[mi][ni][2 * h + 1]);
            }
        }
    }
}

// ---------------- row softmax over NK=2048, fp16 in/out ----------------
__global__ __launch_bounds__(256)
void softmax_rows_h(__half* __restrict__ S)
{
    __half* row = S + (size_t)blockIdx.x * 2048;
    const int tid = threadIdx.x;

    float4 raw = reinterpret_cast<float4*>(row)[tid];   // 8 halfs
    __half2* hp = (__half2*)&raw;
    float2 f[4];
#pragma unroll
    for (int i = 0; i < 4; i++) f[i] = __half22float2(hp[i]);

    float m = fmaxf(fmaxf(fmaxf(f[0].x, f[0].y), fmaxf(f[1].x, f[1].y)),
                    fmaxf(fmaxf(f[2].x, f[2].y), fmaxf(f[3].x, f[3].y)));
#pragma unroll
    for (int o = 16; o; o >>= 1) m = fmaxf(m, __shfl_xor_sync(0xffffffffu, m, o));

    __shared__ float red[8];
    if ((tid & 31) == 0) red[tid >> 5] = m;
    __syncthreads();
    m = red[0];
#pragma unroll
    for (int i = 1; i < 8; i++) m = fmaxf(m, red[i]);

    float s = 0.0f;
#pragma unroll
    for (int i = 0; i < 4; i++) {
        f[i].x = __expf(f[i].x - m);
        f[i].y = __expf(f[i].y - m);
        s += f[i].x + f[i].y;
    }
#pragma unroll
    for (int o = 16; o; o >>= 1) s += __shfl_xor_sync(0xffffffffu, s, o);

    __syncthreads();
    if ((tid & 31) == 0) red[tid >> 5] = s;
    __syncthreads();
    s = red[0];
#pragma unroll
    for (int i = 1; i < 8; i++) s += red[i];

    const float inv = 1.0f / s;
#pragma unroll
    for (int i = 0; i < 4; i++)
        hp[i] = __floats2half2_rn(f[i].x * inv, f[i].y * inv);
    reinterpret_cast<float4*>(row)[tid] = raw;
}

// ---------------- launch ----------------
extern "C" void kernel_launch(void* const* d_in, const int* in_sizes, int n_in,
                              void* d_out, int out_size)
{
    const float* keys    = (const float*)d_in[0];   // [16, 2048, 512]
    const float* queries = (const float*)d_in[1];   // [16, 1024, 512]
    const float* values  = (const float*)d_in[2];   // [16, 2048, 512]
    const int*   mask    = (const int*)  d_in[3];   // [16, 1024, 2048]
    const float* W       = (const float*)d_in[4];   // [256, 512]
    const float* bias    = (const float*)d_in[5];   // [256]
    float* out = (float*)d_out;                     // [16, 1024, 256]

    const int B = 16, NQ = 1024, NK = 2048, D = 512, V = 512, O = 256;
    const float scale = 1.0f / sqrtf(512.0f);       // KQ = 512

    __half *S, *Vt, *Qh, *Kh;
    cudaGetSymbolAddress((void**)&S,  g_S);
    cudaGetSymbolAddress((void**)&Vt, g_Vt);
    cudaGetSymbolAddress((void**)&Qh, g_Qh);
    cudaGetSymbolAddress((void**)&Kh, g_Kh);

    cudaFuncSetAttribute(gemm_a32,   cudaFuncAttributeMaxDynamicSharedMemorySize, SMEM_DB);
    cudaFuncSetAttribute(gemm_cp<1>, cudaFuncAttributeMaxDynamicSharedMemorySize, SMEM_CP);
    cudaFuncSetAttribute(gemm_cp<2>, cudaFuncAttributeMaxDynamicSharedMemorySize, SMEM_CP);

    // Convert Q, K to fp16
    cvt_f2h<<<592, 256>>>((const float4*)queries, (uint2*)Qh, B * NQ * D / 4);
    cvt_f2h<<<592, 256>>>((const float4*)keys,    (uint2*)Kh, B * NK * D / 4);

    // K0: Vt[b][o][n] = sum_v W[o][v] * values[b][n][v]   (fp32 in, fp16 out)
    gemm_a32<<<dim3(NK / BN, O / BM, B), 128, SMEM_DB>>>(
        W, values, Vt, NK, V,
        0LL, (long long)NK * V, (long long)O * NK);

    // K1: S = scale * Qh @ Kh^T, mask==0 -> MASKV   (fp16 in, fp16 out)
    gemm_cp<1><<<dim3(NK / BN, NQ / BM, B), 256, SMEM_CP>>>(
        Qh, Kh, S, NK, D,
        (long long)NQ * D, (long long)NK * D, (long long)NQ * NK,
        mask, (long long)NQ * NK, nullptr, scale);

    // K2: softmax over last dim (fp16)
    softmax_rows_h<<<B * NQ, 256>>>(S);

    // K3: out = P @ Vt^T + bias   (fp16 in, fp32 out)
    gemm_cp<2><<<dim3(O / BN, NQ / BM, B), 256, SMEM_CP>>>(
        S, Vt, out, O, NK,
        (long long)NQ * NK, (long long)O * NK, (long long)NQ * O,
        nullptr, 0LL, bias, 0.0f);
}

// round 10
// speedup vs baseline: 1.0548x; 1.0548x over previous
#include <cuda_runtime.h>
#include <cuda_fp16.h>
#include <stdint.h>

// ---------------- scratch (alloc-free: __device__ globals) ----------------
__device__ __half g_S [16u * 1024u * 2048u];   // logits / probs  [B,NQ,NK]  fp16
__device__ __half g_Vt[16u * 256u  * 2048u];   // V'^T = W @ V^T  [B,O,NK]   fp16
__device__ __half g_Qh[16u * 1024u * 512u];    // queries fp16
__device__ __half g_Kh[16u * 2048u * 512u];    // keys fp16

#define MASKV (-60000.0f)   // fp16-representable "minus infinity"

// ---------------- helpers ----------------
__device__ __forceinline__ uint32_t smem_u32(const void* p) {
    uint32_t a;
    asm("{ .reg .u64 t; cvta.to.shared.u64 t, %1; cvt.u32.u64 %0, t; }" : "=r"(a) : "l"(p));
    return a;
}
__device__ __forceinline__ uint32_t f16x2(float lo, float hi) {
    uint32_t u;
    asm("cvt.rn.f16x2.f32 %0, %1, %2;" : "=r"(u) : "f"(hi), "f"(lo));
    return u;
}
__device__ __forceinline__ void mma_f16(float c[4], const uint32_t a[4], const uint32_t b[2]) {
    asm volatile(
        "mma.sync.aligned.m16n8k16.row.col.f32.f16.f16.f32 "
        "{%0,%1,%2,%3}, {%4,%5,%6,%7}, {%8,%9}, {%0,%1,%2,%3};"
        : "+f"(c[0]), "+f"(c[1]), "+f"(c[2]), "+f"(c[3])
        : "r"(a[0]), "r"(a[1]), "r"(a[2]), "r"(a[3]), "r"(b[0]), "r"(b[1]));
}
__device__ __forceinline__ void ldsm4(uint32_t& r0, uint32_t& r1, uint32_t& r2, uint32_t& r3,
                                      uint32_t addr) {
    asm volatile("ldmatrix.sync.aligned.m8n8.x4.shared.b16 {%0,%1,%2,%3}, [%4];"
                 : "=r"(r0), "=r"(r1), "=r"(r2), "=r"(r3) : "r"(addr));
}
__device__ __forceinline__ void sts64(uint32_t a, uint32_t x, uint32_t y) {
    asm volatile("st.shared.v2.b32 [%0], {%1,%2};" :: "r"(a), "r"(x), "r"(y) : "memory");
}
__device__ __forceinline__ void sts128(uint32_t a, uint4 v) {
    asm volatile("st.shared.v4.b32 [%0], {%1,%2,%3,%4};"
                 :: "r"(a), "r"(v.x), "r"(v.y), "r"(v.z), "r"(v.w) : "memory");
}
__device__ __forceinline__ void cpasync16(uint32_t dst, const void* src) {
    asm volatile("cp.async.cg.shared.global [%0], [%1], 16;" :: "r"(dst), "l"(src) : "memory");
}
#define CP_COMMIT() asm volatile("cp.async.commit_group;" ::: "memory")
#define CP_WAIT2()  asm volatile("cp.async.wait_group 2;" ::: "memory")

// ---------------- tiling ----------------
// CTA tile 128x128x32, 4 warps as 2(M) x 2(N), warp tile 64x64. 128 threads.
// Two CTAs/SM. fp16 smem rows: 64B data, stride 80B (conflict-free ldmatrix).
constexpr int BM = 128, BN = 128, BK = 32;
constexpr int SBH   = 80;                   // bytes per smem row
constexpr int A_B   = BM * SBH;             // 10240
constexpr int STG_B = (BM + BN) * SBH;      // 20480 per stage
constexpr int NSTG  = 4;
constexpr int SMEM_CP = NSTG * STG_B;       // 81920 (cp.async K1)
constexpr int SMEM_DB = 2 * STG_B;          // 40960 (double-buffered kernels)

// ===================== fused fp32 -> fp16 convert for Q and K ==============
__global__ __launch_bounds__(256)
void cvt2_f2h(const float4* __restrict__ srcQ, uint2* __restrict__ dstQ, int n4q,
              const float4* __restrict__ srcK, uint2* __restrict__ dstK, int n4k)
{
    const int total = n4q + n4k;
    for (int i = blockIdx.x * 256 + threadIdx.x; i < total; i += gridDim.x * 256) {
        const float4* s;
        uint2* d;
        int j;
        if (i < n4q) { s = srcQ; d = dstQ; j = i; }
        else         { s = srcK; d = dstK; j = i - n4q; }
        float4 v = s[j];
        uint2 o;
        o.x = f16x2(v.x, v.y);
        o.y = f16x2(v.z, v.w);
        d[j] = o;
    }
}

// ===================== K1: fp16 in, cp.async 4-stage, mask epilogue ========
// S[z][m][n] = scale * sum_k A[z][m][k]*B[z][n][k]; mask==0 -> MASKV. fp16 out.
__global__ __launch_bounds__(128, 2)
void gemm_cp1(const __half* __restrict__ Ag, const __half* __restrict__ Bg,
              __half* __restrict__ Cg, int N, int K,
              long long sA, long long sB, long long sC,
              const int* __restrict__ maskg, long long sMask, float scale)
{
    extern __shared__ char smem[];

    const int tid  = threadIdx.x;
    const int lane = tid & 31;
    const int warp = tid >> 5;
    const int wm = (warp & 1) * 64;
    const int wn = (warp >> 1) * 64;
    const int z  = blockIdx.z;
    const int m0 = blockIdx.y * BM;
    const int n0 = blockIdx.x * BN;

    const __half* A = Ag + (size_t)z * sA;
    const __half* B = Bg + (size_t)z * sB;

    const uint32_t sbase = smem_u32(smem);
    const uint32_t aRowB = (uint32_t)(wm + (lane & 15)) * SBH + (uint32_t)(lane >> 4) * 16;
    const uint32_t bRowB = (uint32_t)(wn + (lane & 7) + ((lane >> 4) << 3)) * SBH
                         + (uint32_t)((lane >> 3) & 1) * 16;
    const int KT = K / BK;

    // one chunk = 8 cp.async x 16B per thread (A 4, B 4)
    const int r4 = tid >> 2;               // 0..31 base row
    const int sg = (tid & 3) * 16;         // 16B segment within 64B row
    auto issue_chunk = [&](int c) {
        const uint32_t st = sbase + (uint32_t)(c & (NSTG - 1)) * STG_B;
        const int koff = c * BK + (tid & 3) * 8;
#pragma unroll
        for (int i = 0; i < 4; i++) {
            int r = r4 + 32 * i;
            cpasync16(st + (uint32_t)r * SBH + sg, A + (size_t)(m0 + r) * K + koff);
        }
#pragma unroll
        for (int i = 0; i < 4; i++) {
            int r = r4 + 32 * i;
            cpasync16(st + (uint32_t)A_B + (uint32_t)r * SBH + sg,
                      B + (size_t)(n0 + r) * K + koff);
        }
    };

    float acc[4][8][4];
#pragma unroll
    for (int i = 0; i < 4; i++)
#pragma unroll
        for (int j = 0; j < 8; j++)
#pragma unroll
            for (int r = 0; r < 4; r++) acc[i][j][r] = 0.0f;

    issue_chunk(0); CP_COMMIT();
    issue_chunk(1); CP_COMMIT();
    issue_chunk(2); CP_COMMIT();

    for (int kb = 0; kb < KT; ++kb) {
        CP_WAIT2();
        __syncthreads();
        if (kb + 3 < KT) issue_chunk(kb + 3);
        CP_COMMIT();

        const uint32_t curBase = sbase + (uint32_t)(kb & (NSTG - 1)) * STG_B;
        const uint32_t aB = curBase + aRowB;
        const uint32_t bB = curBase + (uint32_t)A_B + bRowB;

#pragma unroll
        for (int ks = 0; ks < 2; ++ks) {
            const uint32_t kB = (uint32_t)ks * 32;
            uint32_t af[4][4], bf[8][2];
#pragma unroll
            for (int mi = 0; mi < 4; mi++)
                ldsm4(af[mi][0], af[mi][1], af[mi][2], af[mi][3],
                      aB + (uint32_t)mi * (16 * SBH) + kB);
#pragma unroll
            for (int pr = 0; pr < 4; pr++)
                ldsm4(bf[2 * pr][0], bf[2 * pr][1], bf[2 * pr + 1][0], bf[2 * pr + 1][1],
                      bB + (uint32_t)pr * (16 * SBH) + kB);
#pragma unroll
            for (int mi = 0; mi < 4; mi++)
#pragma unroll
                for (int ni = 0; ni < 8; ni++)
                    mma_f16(acc[mi][ni], af[mi], bf[ni]);
        }
        __syncthreads();
    }

    __half* C = Cg + (size_t)z * sC;
    const int* Mk = maskg + (size_t)z * sMask;
#pragma unroll
    for (int mi = 0; mi < 4; mi++) {
#pragma unroll
        for (int ni = 0; ni < 8; ni++) {
            const int row0 = m0 + wm + mi * 16 + (lane >> 2);
            const int col  = n0 + wn + ni * 8 + (lane & 3) * 2;
#pragma unroll
            for (int h = 0; h < 2; ++h) {
                const int row = row0 + h * 8;
                float v0 = acc[mi][ni][2 * h] * scale;
                float v1 = acc[mi][ni][2 * h + 1] * scale;
                int2 mk = *(const int2*)(Mk + (size_t)row * N + col);
                if (mk.x == 0) v0 = MASKV;
                if (mk.y == 0) v1 = MASKV;
                *(__half2*)(C + (size_t)row * N + col) = __floats2half2_rn(v0, v1);
            }
        }
    }
}

// ===================== K3: fp16 in -> fp32 out + bias (R7 version) =========
__global__ __launch_bounds__(128, 2)
void gemm_h16(const __half* __restrict__ Ag, const __half* __restrict__ Bg,
              float* __restrict__ Cg, int N, int K,
              long long sA, long long sB, long long sC,
              const float* __restrict__ bias)
{
    extern __shared__ char smem[];

    const int tid  = threadIdx.x;
    const int lane = tid & 31;
    const int warp = tid >> 5;
    const int wm = (warp & 1) * 64;
    const int wn = (warp >> 1) * 64;
    const int z  = blockIdx.z;
    const int m0 = blockIdx.y * BM;
    const int n0 = blockIdx.x * BN;

    const __half* A = Ag + (size_t)z * sA;
    const __half* B = Bg + (size_t)z * sB;

    const uint32_t sbase = smem_u32(smem);
    const uint32_t aRowB = (uint32_t)(wm + (lane & 15)) * SBH + (uint32_t)(lane >> 4) * 16;
    const uint32_t bRowB = (uint32_t)(wn + (lane & 7) + ((lane >> 4) << 3)) * SBH
                         + (uint32_t)((lane >> 3) & 1) * 16;
    const int KT = K / BK;

    uint4 ra[4], rb[4];
    auto load_regs = [&](int c) {
        const int koff = c * BK;
#pragma unroll
        for (int i = 0; i < 4; i++) {
            int f = tid + 128 * i, r = f >> 2, sg = f & 3;
            ra[i] = *(const uint4*)(A + (size_t)(m0 + r) * K + koff + sg * 8);
        }
#pragma unroll
        for (int i = 0; i < 4; i++) {
            int f = tid + 128 * i, r = f >> 2, sg = f & 3;
            rb[i] = *(const uint4*)(B + (size_t)(n0 + r) * K + koff + sg * 8);
        }
    };
    auto store_stage = [&](int s) {
        const uint32_t st = sbase + (uint32_t)s * STG_B;
#pragma unroll
        for (int i = 0; i < 4; i++) {
            int f = tid + 128 * i, r = f >> 2, sg = f & 3;
            sts128(st + (uint32_t)r * SBH + (uint32_t)sg * 16, ra[i]);
        }
#pragma unroll
        for (int i = 0; i < 4; i++) {
            int f = tid + 128 * i, r = f >> 2, sg = f & 3;
            sts128(st + (uint32_t)A_B + (uint32_t)r * SBH + (uint32_t)sg * 16, rb[i]);
        }
    };

    float acc[4][8][4];
#pragma unroll
    for (int i = 0; i < 4; i++)
#pragma unroll
        for (int j = 0; j < 8; j++)
#pragma unroll
            for (int r = 0; r < 4; r++) acc[i][j][r] = 0.0f;

    load_regs(0);
    store_stage(0);
    __syncthreads();
    if (KT > 1) load_regs(1);

    for (int kb = 0; kb < KT; ++kb) {
        const int cur = kb & 1;
        if (kb + 1 < KT) store_stage(cur ^ 1);
        if (kb + 2 < KT) load_regs(kb + 2);

        const uint32_t curBase = sbase + (uint32_t)cur * STG_B;
        const uint32_t aB = curBase + aRowB;
        const uint32_t bB = curBase + (uint32_t)A_B + bRowB;

#pragma unroll
        for (int ks = 0; ks < 2; ++ks) {
            const uint32_t kB = (uint32_t)ks * 32;
            uint32_t af[4][4], bf[8][2];
#pragma unroll
            for (int mi = 0; mi < 4; mi++)
                ldsm4(af[mi][0], af[mi][1], af[mi][2], af[mi][3],
                      aB + (uint32_t)mi * (16 * SBH) + kB);
#pragma unroll
            for (int pr = 0; pr < 4; pr++)
                ldsm4(bf[2 * pr][0], bf[2 * pr][1], bf[2 * pr + 1][0], bf[2 * pr + 1][1],
                      bB + (uint32_t)pr * (16 * SBH) + kB);
#pragma unroll
            for (int mi = 0; mi < 4; mi++)
#pragma unroll
                for (int ni = 0; ni < 8; ni++)
                    mma_f16(acc[mi][ni], af[mi], bf[ni]);
        }
        __syncthreads();
    }

    float* C = Cg + (size_t)z * sC;
#pragma unroll
    for (int mi = 0; mi < 4; mi++) {
#pragma unroll
        for (int ni = 0; ni < 8; ni++) {
            const int row0 = m0 + wm + mi * 16 + (lane >> 2);
            const int col  = n0 + wn + ni * 8 + (lane & 3) * 2;
            const float b0 = bias[col], b1 = bias[col + 1];
#pragma unroll
            for (int h = 0; h < 2; ++h) {
                const int row = row0 + h * 8;
                float2 o;
                o.x = acc[mi][ni][2 * h]     + b0;
                o.y = acc[mi][ni][2 * h + 1] + b1;
                *(float2*)(C + (size_t)row * N + col) = o;
            }
        }
    }
}

// ===================== K0: fp32 inputs -> fp16 out =========================
__global__ __launch_bounds__(128, 2)
void gemm_a32(const float* __restrict__ Ag, const float* __restrict__ Bg,
              __half* __restrict__ Cg, int N, int K,
              long long sA, long long sB, long long sC)
{
    extern __shared__ char smem[];

    const int tid  = threadIdx.x;
    const int lane = tid & 31;
    const int warp = tid >> 5;
    const int wm = (warp & 1) * 64;
    const int wn = (warp >> 1) * 64;
    const int z  = blockIdx.z;
    const int m0 = blockIdx.y * BM;
    const int n0 = blockIdx.x * BN;

    const float* A = Ag + (size_t)z * sA;
    const float* B = Bg + (size_t)z * sB;

    const uint32_t sbase = smem_u32(smem);
    const uint32_t aRowB = (uint32_t)(wm + (lane & 15)) * SBH + (uint32_t)(lane >> 4) * 16;
    const uint32_t bRowB = (uint32_t)(wn + (lane & 7) + ((lane >> 4) << 3)) * SBH
                         + (uint32_t)((lane >> 3) & 1) * 16;
    const int KT = K / BK;

    float4 ra[8], rb[8];
    auto load_regs = [&](int c) {
        const int koff = c * BK;
#pragma unroll
        for (int i = 0; i < 8; i++) {
            int f = tid + 128 * i, r = f >> 3, q = (f & 7) * 4;
            ra[i] = *(const float4*)(A + (size_t)(m0 + r) * K + koff + q);
        }
#pragma unroll
        for (int i = 0; i < 8; i++) {
            int f = tid + 128 * i, r = f >> 3, q = (f & 7) * 4;
            rb[i] = *(const float4*)(B + (size_t)(n0 + r) * K + koff + q);
        }
    };
    auto store_stage = [&](int s) {
        const uint32_t st = sbase + (uint32_t)s * STG_B;
#pragma unroll
        for (int i = 0; i < 8; i++) {
            int f = tid + 128 * i, r = f >> 3, q = (f & 7) * 4;
            sts64(st + (uint32_t)r * SBH + (uint32_t)q * 2,
                  f16x2(ra[i].x, ra[i].y), f16x2(ra[i].z, ra[i].w));
        }
#pragma unroll
        for (int i = 0; i < 8; i++) {
            int f = tid + 128 * i, r = f >> 3, q = (f & 7) * 4;
            sts64(st + (uint32_t)A_B + (uint32_t)r * SBH + (uint32_t)q * 2,
                  f16x2(rb[i].x, rb[i].y), f16x2(rb[i].z, rb[i].w));
        }
    };

    float acc[4][8][4];
#pragma unroll
    for (int i = 0; i < 4; i++)
#pragma unroll
        for (int j = 0; j < 8; j++)
#pragma unroll
            for (int r = 0; r < 4; r++) acc[i][j][r] = 0.0f;

    load_regs(0);
    store_stage(0);
    __syncthreads();
    if (KT > 1) load_regs(1);

    for (int kb = 0; kb < KT; ++kb) {
        const int cur = kb & 1;
        if (kb + 1 < KT) store_stage(cur ^ 1);
        if (kb + 2 < KT) load_regs(kb + 2);

        const uint32_t curBase = sbase + (uint32_t)cur * STG_B;
        const uint32_t aB = curBase + aRowB;
        const uint32_t bB = curBase + (uint32_t)A_B + bRowB;

#pragma unroll
        for (int ks = 0; ks < 2; ++ks) {
            const uint32_t kB = (uint32_t)ks * 32;
            uint32_t af[4][4], bf[8][2];
#pragma unroll
            for (int mi = 0; mi < 4; mi++)
                ldsm4(af[mi][0], af[mi][1], af[mi][2], af[mi][3],
                      aB + (uint32_t)mi * (16 * SBH) + kB);
#pragma unroll
            for (int pr = 0; pr < 4; pr++)
                ldsm4(bf[2 * pr][0], bf[2 * pr][1], bf[2 * pr + 1][0], bf[2 * pr + 1][1],
                      bB + (uint32_t)pr * (16 * SBH) + kB);
#pragma unroll
            for (int mi = 0; mi < 4; mi++)
#pragma unroll
                for (int ni = 0; ni < 8; ni++)
                    mma_f16(acc[mi][ni], af[mi], bf[ni]);
        }
        __syncthreads();
    }

    __half* C = Cg + (size_t)z * sC;
#pragma unroll
    for (int mi = 0; mi < 4; mi++) {
#pragma unroll
        for (int ni = 0; ni < 8; ni++) {
            const int row0 = m0 + wm + mi * 16 + (lane >> 2);
            const int col  = n0 + wn + ni * 8 + (lane & 3) * 2;
#pragma unroll
            for (int h = 0; h < 2; ++h) {
                const int row = row0 + h * 8;
                *(__half2*)(C + (size_t)row * N + col) =
                    __floats2half2_rn(acc[mi][ni][2 * h], acc[mi][ni][2 * h + 1]);
            }
        }
    }
}

// ---------------- row softmax over NK=2048, fp16 in/out ----------------
__global__ __launch_bounds__(256)
void softmax_rows_h(__half* __restrict__ S)
{
    __half* row = S + (size_t)blockIdx.x * 2048;
    const int tid = threadIdx.x;

    float4 raw = reinterpret_cast<float4*>(row)[tid];   // 8 halfs
    __half2* hp = (__half2*)&raw;
    float2 f[4];
#pragma unroll
    for (int i = 0; i < 4; i++) f[i] = __half22float2(hp[i]);

    float m = fmaxf(fmaxf(fmaxf(f[0].x, f[0].y), fmaxf(f[1].x, f[1].y)),
                    fmaxf(fmaxf(f[2].x, f[2].y), fmaxf(f[3].x, f[3].y)));
#pragma unroll
    for (int o = 16; o; o >>= 1) m = fmaxf(m, __shfl_xor_sync(0xffffffffu, m, o));

    __shared__ float red[8];
    if ((tid & 31) == 0) red[tid >> 5] = m;
    __syncthreads();
    m = red[0];
#pragma unroll
    for (int i = 1; i < 8; i++) m = fmaxf(m, red[i]);

    float s = 0.0f;
#pragma unroll
    for (int i = 0; i < 4; i++) {
        f[i].x = __expf(f[i].x - m);
        f[i].y = __expf(f[i].y - m);
        s += f[i].x + f[i].y;
    }
#pragma unroll
    for (int o = 16; o; o >>= 1) s += __shfl_xor_sync(0xffffffffu, s, o);

    __syncthreads();
    if ((tid & 31) == 0) red[tid >> 5] = s;
    __syncthreads();
    s = red[0];
#pragma unroll
    for (int i = 1; i < 8; i++) s += red[i];

    const float inv = 1.0f / s;
#pragma unroll
    for (int i = 0; i < 4; i++)
        hp[i] = __floats2half2_rn(f[i].x * inv, f[i].y * inv);
    reinterpret_cast<float4*>(row)[tid] = raw;
}

// ---------------- launch ----------------
extern "C" void kernel_launch(void* const* d_in, const int* in_sizes, int n_in,
                              void* d_out, int out_size)
{
    const float* keys    = (const float*)d_in[0];   // [16, 2048, 512]
    const float* queries = (const float*)d_in[1];   // [16, 1024, 512]
    const float* values  = (const float*)d_in[2];   // [16, 2048, 512]
    const int*   mask    = (const int*)  d_in[3];   // [16, 1024, 2048]
    const float* W       = (const float*)d_in[4];   // [256, 512]
    const float* bias    = (const float*)d_in[5];   // [256]
    float* out = (float*)d_out;                     // [16, 1024, 256]

    const int B = 16, NQ = 1024, NK = 2048, D = 512, V = 512, O = 256;
    const float scale = 1.0f / sqrtf(512.0f);       // KQ = 512

    __half *S, *Vt, *Qh, *Kh;
    cudaGetSymbolAddress((void**)&S,  g_S);
    cudaGetSymbolAddress((void**)&Vt, g_Vt);
    cudaGetSymbolAddress((void**)&Qh, g_Qh);
    cudaGetSymbolAddress((void**)&Kh, g_Kh);

    cudaFuncSetAttribute(gemm_a32, cudaFuncAttributeMaxDynamicSharedMemorySize, SMEM_DB);
    cudaFuncSetAttribute(gemm_cp1, cudaFuncAttributeMaxDynamicSharedMemorySize, SMEM_CP);
    cudaFuncSetAttribute(gemm_h16, cudaFuncAttributeMaxDynamicSharedMemorySize, SMEM_DB);

    // Convert Q and K to fp16 in one launch
    cvt2_f2h<<<888, 256>>>((const float4*)queries, (uint2*)Qh, B * NQ * D / 4,
                           (const float4*)keys,    (uint2*)Kh, B * NK * D / 4);

    // K0: Vt[b][o][n] = sum_v W[o][v] * values[b][n][v]   (fp32 in, fp16 out)
    gemm_a32<<<dim3(NK / BN, O / BM, B), 128, SMEM_DB>>>(
        W, values, Vt, NK, V,
        0LL, (long long)NK * V, (long long)O * NK);

    // K1: S = scale * Qh @ Kh^T, mask==0 -> MASKV   (fp16 in, fp16 out)
    gemm_cp1<<<dim3(NK / BN, NQ / BM, B), 128, SMEM_CP>>>(
        Qh, Kh, S, NK, D,
        (long long)NQ * D, (long long)NK * D, (long long)NQ * NK,
        mask, (long long)NQ * NK, scale);

    // K2: softmax over last dim (fp16)
    softmax_rows_h<<<B * NQ, 256>>>(S);

    // K3: out = P @ Vt^T + bias   (fp16 in, fp32 out)
    gemm_h16<<<dim3(O / BN, NQ / BM, B), 128, SMEM_DB>>>(
        S, Vt, out, O, NK,
        (long long)NQ * NK, (long long)O * NK, (long long)NQ * O,
        bias);
}

// round 11
// speedup vs baseline: 1.0684x; 1.0129x over previous
#include <cuda_runtime.h>
#include <cuda_fp16.h>
#include <stdint.h>

// ---------------- scratch (alloc-free: __device__ globals) ----------------
__device__ __half g_S [16u * 1024u * 2048u];   // exp(logits), unnormalized  [B,NQ,NK] fp16
__device__ __half g_Vt[16u * 256u  * 2048u];   // V'^T = W @ V^T  [B,O,NK]   fp16
__device__ __half g_Qh[16u * 1024u * 512u];    // queries fp16
__device__ __half g_Kh[16u * 2048u * 512u];    // keys fp16
__device__ float  g_rsum[16u * 1024u];         // per-row sum of exp(logits)

// ---------------- helpers ----------------
__device__ __forceinline__ uint32_t smem_u32(const void* p) {
    uint32_t a;
    asm("{ .reg .u64 t; cvta.to.shared.u64 t, %1; cvt.u32.u64 %0, t; }" : "=r"(a) : "l"(p));
    return a;
}
__device__ __forceinline__ uint32_t f16x2(float lo, float hi) {
    uint32_t u;
    asm("cvt.rn.f16x2.f32 %0, %1, %2;" : "=r"(u) : "f"(hi), "f"(lo));
    return u;
}
__device__ __forceinline__ void mma_f16(float c[4], const uint32_t a[4], const uint32_t b[2]) {
    asm volatile(
        "mma.sync.aligned.m16n8k16.row.col.f32.f16.f16.f32 "
        "{%0,%1,%2,%3}, {%4,%5,%6,%7}, {%8,%9}, {%0,%1,%2,%3};"
        : "+f"(c[0]), "+f"(c[1]), "+f"(c[2]), "+f"(c[3])
        : "r"(a[0]), "r"(a[1]), "r"(a[2]), "r"(a[3]), "r"(b[0]), "r"(b[1]));
}
__device__ __forceinline__ void ldsm4(uint32_t& r0, uint32_t& r1, uint32_t& r2, uint32_t& r3,
                                      uint32_t addr) {
    asm volatile("ldmatrix.sync.aligned.m8n8.x4.shared.b16 {%0,%1,%2,%3}, [%4];"
                 : "=r"(r0), "=r"(r1), "=r"(r2), "=r"(r3) : "r"(addr));
}
__device__ __forceinline__ void sts64(uint32_t a, uint32_t x, uint32_t y) {
    asm volatile("st.shared.v2.b32 [%0], {%1,%2};" :: "r"(a), "r"(x), "r"(y) : "memory");
}
__device__ __forceinline__ void sts128(uint32_t a, uint4 v) {
    asm volatile("st.shared.v4.b32 [%0], {%1,%2,%3,%4};"
                 :: "r"(a), "r"(v.x), "r"(v.y), "r"(v.z), "r"(v.w) : "memory");
}
__device__ __forceinline__ void cpasync16(uint32_t dst, const void* src) {
    asm volatile("cp.async.cg.shared.global [%0], [%1], 16;" :: "r"(dst), "l"(src) : "memory");
}
#define CP_COMMIT() asm volatile("cp.async.commit_group;" ::: "memory")
#define CP_WAIT2()  asm volatile("cp.async.wait_group 2;" ::: "memory")

// ---------------- tiling ----------------
// CTA tile 128x128x32, 4 warps as 2(M) x 2(N), warp tile 64x64. 128 threads.
// Two CTAs/SM. fp16 smem rows: 64B data, stride 80B (conflict-free ldmatrix).
constexpr int BM = 128, BN = 128, BK = 32;
constexpr int SBH   = 80;                   // bytes per smem row
constexpr int A_B   = BM * SBH;             // 10240
constexpr int STG_B = (BM + BN) * SBH;      // 20480 per stage
constexpr int NSTG  = 4;
constexpr int SMEM_CP = NSTG * STG_B;       // 81920 (cp.async K1)
constexpr int SMEM_DB = 2 * STG_B;          // 40960 (double-buffered kernels)

// ======= fused fp32 -> fp16 convert for Q and K + zero row_sum =============
__global__ __launch_bounds__(256)
void cvt2_f2h(const float4* __restrict__ srcQ, uint2* __restrict__ dstQ, int n4q,
              const float4* __restrict__ srcK, uint2* __restrict__ dstK, int n4k,
              float4* __restrict__ rs4, int nrs4)
{
    const int gid = blockIdx.x * 256 + threadIdx.x;
    if (gid < nrs4) rs4[gid] = make_float4(0.f, 0.f, 0.f, 0.f);
    const int total = n4q + n4k;
    for (int i = gid; i < total; i += gridDim.x * 256) {
        const float4* s;
        uint2* d;
        int j;
        if (i < n4q) { s = srcQ; d = dstQ; j = i; }
        else         { s = srcK; d = dstK; j = i - n4q; }
        float4 v = s[j];
        uint2 o;
        o.x = f16x2(v.x, v.y);
        o.y = f16x2(v.z, v.w);
        d[j] = o;
    }
}

// ===================== K1: fp16 in, cp.async 4-stage =======================
// Writes P = exp(scale * (Q.K)) (masked -> 0) in fp16, and accumulates
// per-row sums of P into rsum via atomics (no separate softmax kernel).
__global__ __launch_bounds__(128, 2)
void gemm_cp1(const __half* __restrict__ Ag, const __half* __restrict__ Bg,
              __half* __restrict__ Cg, int N, int K,
              long long sA, long long sB, long long sC,
              const int* __restrict__ maskg, long long sMask,
              float* __restrict__ rsum, float scale)
{
    extern __shared__ char smem[];

    const int tid  = threadIdx.x;
    const int lane = tid & 31;
    const int warp = tid >> 5;
    const int wm = (warp & 1) * 64;
    const int wn = (warp >> 1) * 64;
    const int z  = blockIdx.z;
    const int m0 = blockIdx.y * BM;
    const int n0 = blockIdx.x * BN;

    const __half* A = Ag + (size_t)z * sA;
    const __half* B = Bg + (size_t)z * sB;

    const uint32_t sbase = smem_u32(smem);
    const uint32_t aRowB = (uint32_t)(wm + (lane & 15)) * SBH + (uint32_t)(lane >> 4) * 16;
    const uint32_t bRowB = (uint32_t)(wn + (lane & 7) + ((lane >> 4) << 3)) * SBH
                         + (uint32_t)((lane >> 3) & 1) * 16;
    const int KT = K / BK;

    // one chunk = 8 cp.async x 16B per thread (A 4, B 4)
    const int r4 = tid >> 2;               // 0..31 base row
    const int sg = (tid & 3) * 16;         // 16B segment within 64B row
    auto issue_chunk = [&](int c) {
        const uint32_t st = sbase + (uint32_t)(c & (NSTG - 1)) * STG_B;
        const int koff = c * BK + (tid & 3) * 8;
#pragma unroll
        for (int i = 0; i < 4; i++) {
            int r = r4 + 32 * i;
            cpasync16(st + (uint32_t)r * SBH + sg, A + (size_t)(m0 + r) * K + koff);
        }
#pragma unroll
        for (int i = 0; i < 4; i++) {
            int r = r4 + 32 * i;
            cpasync16(st + (uint32_t)A_B + (uint32_t)r * SBH + sg,
                      B + (size_t)(n0 + r) * K + koff);
        }
    };

    float acc[4][8][4];
#pragma unroll
    for (int i = 0; i < 4; i++)
#pragma unroll
        for (int j = 0; j < 8; j++)
#pragma unroll
            for (int r = 0; r < 4; r++) acc[i][j][r] = 0.0f;

    issue_chunk(0); CP_COMMIT();
    issue_chunk(1); CP_COMMIT();
    issue_chunk(2); CP_COMMIT();

    for (int kb = 0; kb < KT; ++kb) {
        CP_WAIT2();
        __syncthreads();
        if (kb + 3 < KT) issue_chunk(kb + 3);
        CP_COMMIT();

        const uint32_t curBase = sbase + (uint32_t)(kb & (NSTG - 1)) * STG_B;
        const uint32_t aB = curBase + aRowB;
        const uint32_t bB = curBase + (uint32_t)A_B + bRowB;

#pragma unroll
        for (int ks = 0; ks < 2; ++ks) {
            const uint32_t kB = (uint32_t)ks * 32;
            uint32_t af[4][4], bf[8][2];
#pragma unroll
            for (int mi = 0; mi < 4; mi++)
                ldsm4(af[mi][0], af[mi][1], af[mi][2], af[mi][3],
                      aB + (uint32_t)mi * (16 * SBH) + kB);
#pragma unroll
            for (int pr = 0; pr < 4; pr++)
                ldsm4(bf[2 * pr][0], bf[2 * pr][1], bf[2 * pr + 1][0], bf[2 * pr + 1][1],
                      bB + (uint32_t)pr * (16 * SBH) + kB);
#pragma unroll
            for (int mi = 0; mi < 4; mi++)
#pragma unroll
                for (int ni = 0; ni < 8; ni++)
                    mma_f16(acc[mi][ni], af[mi], bf[ni]);
        }
        __syncthreads();
    }

    // ---- epilogue: exp + mask -> store P, reduce row partial sums ----
    __half* C = Cg + (size_t)z * sC;
    const int* Mk = maskg + (size_t)z * sMask;
    float* RS = rsum + (size_t)z * 1024;

#pragma unroll
    for (int mi = 0; mi < 4; mi++) {
        const int row0 = m0 + wm + mi * 16 + (lane >> 2);
        float psum[2] = {0.0f, 0.0f};
#pragma unroll
        for (int ni = 0; ni < 8; ni++) {
            const int col = n0 + wn + ni * 8 + (lane & 3) * 2;
#pragma unroll
            for (int h = 0; h < 2; ++h) {
                const int row = row0 + h * 8;
                int2 mk = *(const int2*)(Mk + (size_t)row * N + col);
                float v0 = mk.x ? __expf(acc[mi][ni][2 * h] * scale)     : 0.0f;
                float v1 = mk.y ? __expf(acc[mi][ni][2 * h + 1] * scale) : 0.0f;
                psum[h] += v0 + v1;
                *(__half2*)(C + (size_t)row * N + col) = __floats2half2_rn(v0, v1);
            }
        }
#pragma unroll
        for (int h = 0; h < 2; ++h) {
            float s = psum[h];
            s += __shfl_xor_sync(0xffffffffu, s, 1);
            s += __shfl_xor_sync(0xffffffffu, s, 2);
            if ((lane & 3) == 0) atomicAdd(RS + row0 + h * 8, s);
        }
    }
}

// ===================== K3: fp16 in -> fp32 out, scale by 1/rowsum + bias ===
__global__ __launch_bounds__(128, 2)
void gemm_h16(const __half* __restrict__ Ag, const __half* __restrict__ Bg,
              float* __restrict__ Cg, int N, int K,
              long long sA, long long sB, long long sC,
              const float* __restrict__ bias, const float* __restrict__ rsum)
{
    extern __shared__ char smem[];

    const int tid  = threadIdx.x;
    const int lane = tid & 31;
    const int warp = tid >> 5;
    const int wm = (warp & 1) * 64;
    const int wn = (warp >> 1) * 64;
    const int z  = blockIdx.z;
    const int m0 = blockIdx.y * BM;
    const int n0 = blockIdx.x * BN;

    const __half* A = Ag + (size_t)z * sA;
    const __half* B = Bg + (size_t)z * sB;

    const uint32_t sbase = smem_u32(smem);
    const uint32_t aRowB = (uint32_t)(wm + (lane & 15)) * SBH + (uint32_t)(lane >> 4) * 16;
    const uint32_t bRowB = (uint32_t)(wn + (lane & 7) + ((lane >> 4) << 3)) * SBH
                         + (uint32_t)((lane >> 3) & 1) * 16;
    const int KT = K / BK;

    uint4 ra[4], rb[4];
    auto load_regs = [&](int c) {
        const int koff = c * BK;
#pragma unroll
        for (int i = 0; i < 4; i++) {
            int f = tid + 128 * i, r = f >> 2, sg = f & 3;
            ra[i] = *(const uint4*)(A + (size_t)(m0 + r) * K + koff + sg * 8);
        }
#pragma unroll
        for (int i = 0; i < 4; i++) {
            int f = tid + 128 * i, r = f >> 2, sg = f & 3;
            rb[i] = *(const uint4*)(B + (size_t)(n0 + r) * K + koff + sg * 8);
        }
    };
    auto store_stage = [&](int s) {
        const uint32_t st = sbase + (uint32_t)s * STG_B;
#pragma unroll
        for (int i = 0; i < 4; i++) {
            int f = tid + 128 * i, r = f >> 2, sg = f & 3;
            sts128(st + (uint32_t)r * SBH + (uint32_t)sg * 16, ra[i]);
        }
#pragma unroll
        for (int i = 0; i < 4; i++) {
            int f = tid + 128 * i, r = f >> 2, sg = f & 3;
            sts128(st + (uint32_t)A_B + (uint32_t)r * SBH + (uint32_t)sg * 16, rb[i]);
        }
    };

    float acc[4][8][4];
#pragma unroll
    for (int i = 0; i < 4; i++)
#pragma unroll
        for (int j = 0; j < 8; j++)
#pragma unroll
            for (int r = 0; r < 4; r++) acc[i][j][r] = 0.0f;

    load_regs(0);
    store_stage(0);
    __syncthreads();
    if (KT > 1) load_regs(1);

    for (int kb = 0; kb < KT; ++kb) {
        const int cur = kb & 1;
        if (kb + 1 < KT) store_stage(cur ^ 1);
        if (kb + 2 < KT) load_regs(kb + 2);

        const uint32_t curBase = sbase + (uint32_t)cur * STG_B;
        const uint32_t aB = curBase + aRowB;
        const uint32_t bB = curBase + (uint32_t)A_B + bRowB;

#pragma unroll
        for (int ks = 0; ks < 2; ++ks) {
            const uint32_t kB = (uint32_t)ks * 32;
            uint32_t af[4][4], bf[8][2];
#pragma unroll
            for (int mi = 0; mi < 4; mi++)
                ldsm4(af[mi][0], af[mi][1], af[mi][2], af[mi][3],
                      aB + (uint32_t)mi * (16 * SBH) + kB);
#pragma unroll
            for (int pr = 0; pr < 4; pr++)
                ldsm4(bf[2 * pr][0], bf[2 * pr][1], bf[2 * pr + 1][0], bf[2 * pr + 1][1],
                      bB + (uint32_t)pr * (16 * SBH) + kB);
#pragma unroll
            for (int mi = 0; mi < 4; mi++)
#pragma unroll
                for (int ni = 0; ni < 8; ni++)
                    mma_f16(acc[mi][ni], af[mi], bf[ni]);
        }
        __syncthreads();
    }

    float* C = Cg + (size_t)z * sC;
    const float* RS = rsum + (size_t)z * 1024;
#pragma unroll
    for (int mi = 0; mi < 4; mi++) {
        const int row0 = m0 + wm + mi * 16 + (lane >> 2);
        const float inv0 = 1.0f / RS[row0];
        const float inv1 = 1.0f / RS[row0 + 8];
#pragma unroll
        for (int ni = 0; ni < 8; ni++) {
            const int col = n0 + wn + ni * 8 + (lane & 3) * 2;
            const float b0 = bias[col], b1 = bias[col + 1];
            float2 o;
            o.x = acc[mi][ni][0] * inv0 + b0;
            o.y = acc[mi][ni][1] * inv0 + b1;
            *(float2*)(C + (size_t)row0 * N + col) = o;
            o.x = acc[mi][ni][2] * inv1 + b0;
            o.y = acc[mi][ni][3] * inv1 + b1;
            *(float2*)(C + (size_t)(row0 + 8) * N + col) = o;
        }
    }
}

// ===================== K0: fp32 inputs -> fp16 out =========================
__global__ __launch_bounds__(128, 2)
void gemm_a32(const float* __restrict__ Ag, const float* __restrict__ Bg,
              __half* __restrict__ Cg, int N, int K,
              long long sA, long long sB, long long sC)
{
    extern __shared__ char smem[];

    const int tid  = threadIdx.x;
    const int lane = tid & 31;
    const int warp = tid >> 5;
    const int wm = (warp & 1) * 64;
    const int wn = (warp >> 1) * 64;
    const int z  = blockIdx.z;
    const int m0 = blockIdx.y * BM;
    const int n0 = blockIdx.x * BN;

    const float* A = Ag + (size_t)z * sA;
    const float* B = Bg + (size_t)z * sB;

    const uint32_t sbase = smem_u32(smem);
    const uint32_t aRowB = (uint32_t)(wm + (lane & 15)) * SBH + (uint32_t)(lane >> 4) * 16;
    const uint32_t bRowB = (uint32_t)(wn + (lane & 7) + ((lane >> 4) << 3)) * SBH
                         + (uint32_t)((lane >> 3) & 1) * 16;
    const int KT = K / BK;

    float4 ra[8], rb[8];
    auto load_regs = [&](int c) {
        const int koff = c * BK;
#pragma unroll
        for (int i = 0; i < 8; i++) {
            int f = tid + 128 * i, r = f >> 3, q = (f & 7) * 4;
            ra[i] = *(const float4*)(A + (size_t)(m0 + r) * K + koff + q);
        }
#pragma unroll
        for (int i = 0; i < 8; i++) {
            int f = tid + 128 * i, r = f >> 3, q = (f & 7) * 4;
            rb[i] = *(const float4*)(B + (size_t)(n0 + r) * K + koff + q);
        }
    };
    auto store_stage = [&](int s) {
        const uint32_t st = sbase + (uint32_t)s * STG_B;
#pragma unroll
        for (int i = 0; i < 8; i++) {
            int f = tid + 128 * i, r = f >> 3, q = (f & 7) * 4;
            sts64(st + (uint32_t)r * SBH + (uint32_t)q * 2,
                  f16x2(ra[i].x, ra[i].y), f16x2(ra[i].z, ra[i].w));
        }
#pragma unroll
        for (int i = 0; i < 8; i++) {
            int f = tid + 128 * i, r = f >> 3, q = (f & 7) * 4;
            sts64(st + (uint32_t)A_B + (uint32_t)r * SBH + (uint32_t)q * 2,
                  f16x2(rb[i].x, rb[i].y), f16x2(rb[i].z, rb[i].w));
        }
    };

    float acc[4][8][4];
#pragma unroll
    for (int i = 0; i < 4; i++)
#pragma unroll
        for (int j = 0; j < 8; j++)
#pragma unroll
            for (int r = 0; r < 4; r++) acc[i][j][r] = 0.0f;

    load_regs(0);
    store_stage(0);
    __syncthreads();
    if (KT > 1) load_regs(1);

    for (int kb = 0; kb < KT; ++kb) {
        const int cur = kb & 1;
        if (kb + 1 < KT) store_stage(cur ^ 1);
        if (kb + 2 < KT) load_regs(kb + 2);

        const uint32_t curBase = sbase + (uint32_t)cur * STG_B;
        const uint32_t aB = curBase + aRowB;
        const uint32_t bB = curBase + (uint32_t)A_B + bRowB;

#pragma unroll
        for (int ks = 0; ks < 2; ++ks) {
            const uint32_t kB = (uint32_t)ks * 32;
            uint32_t af[4][4], bf[8][2];
#pragma unroll
            for (int mi = 0; mi < 4; mi++)
                ldsm4(af[mi][0], af[mi][1], af[mi][2], af[mi][3],
                      aB + (uint32_t)mi * (16 * SBH) + kB);
#pragma unroll
            for (int pr = 0; pr < 4; pr++)
                ldsm4(bf[2 * pr][0], bf[2 * pr][1], bf[2 * pr + 1][0], bf[2 * pr + 1][1],
                      bB + (uint32_t)pr * (16 * SBH) + kB);
#pragma unroll
            for (int mi = 0; mi < 4; mi++)
#pragma unroll
                for (int ni = 0; ni < 8; ni++)
                    mma_f16(acc[mi][ni], af[mi], bf[ni]);
        }
        __syncthreads();
    }

    __half* C = Cg + (size_t)z * sC;
#pragma unroll
    for (int mi = 0; mi < 4; mi++) {
#pragma unroll
        for (int ni = 0; ni < 8; ni++) {
            const int row0 = m0 + wm + mi * 16 + (lane >> 2);
            const int col  = n0 + wn + ni * 8 + (lane & 3) * 2;
#pragma unroll
            for (int h = 0; h < 2; ++h) {
                const int row = row0 + h * 8;
                *(__half2*)(C + (size_t)row * N + col) =
                    __floats2half2_rn(acc[mi][ni][2 * h], acc[mi][ni][2 * h + 1]);
            }
        }
    }
}

// ---------------- launch ----------------
extern "C" void kernel_launch(void* const* d_in, const int* in_sizes, int n_in,
                              void* d_out, int out_size)
{
    const float* keys    = (const float*)d_in[0];   // [16, 2048, 512]
    const float* queries = (const float*)d_in[1];   // [16, 1024, 512]
    const float* values  = (const float*)d_in[2];   // [16, 2048, 512]
    const int*   mask    = (const int*)  d_in[3];   // [16, 1024, 2048]
    const float* W       = (const float*)d_in[4];   // [256, 512]
    const float* bias    = (const float*)d_in[5];   // [256]
    float* out = (float*)d_out;                     // [16, 1024, 256]

    const int B = 16, NQ = 1024, NK = 2048, D = 512, V = 512, O = 256;
    const float scale = 1.0f / sqrtf(512.0f);       // KQ = 512

    __half *S, *Vt, *Qh, *Kh;
    float* RS;
    cudaGetSymbolAddress((void**)&S,  g_S);
    cudaGetSymbolAddress((void**)&Vt, g_Vt);
    cudaGetSymbolAddress((void**)&Qh, g_Qh);
    cudaGetSymbolAddress((void**)&Kh, g_Kh);
    cudaGetSymbolAddress((void**)&RS, g_rsum);

    cudaFuncSetAttribute(gemm_a32, cudaFuncAttributeMaxDynamicSharedMemorySize, SMEM_DB);
    cudaFuncSetAttribute(gemm_cp1, cudaFuncAttributeMaxDynamicSharedMemorySize, SMEM_CP);
    cudaFuncSetAttribute(gemm_h16, cudaFuncAttributeMaxDynamicSharedMemorySize, SMEM_DB);

    // Convert Q and K to fp16 + zero row sums (one launch)
    cvt2_f2h<<<888, 256>>>((const float4*)queries, (uint2*)Qh, B * NQ * D / 4,
                           (const float4*)keys,    (uint2*)Kh, B * NK * D / 4,
                           (float4*)RS, B * NQ / 4);

    // K0: Vt[b][o][n] = sum_v W[o][v] * values[b][n][v]   (fp32 in, fp16 out)
    gemm_a32<<<dim3(NK / BN, O / BM, B), 128, SMEM_DB>>>(
        W, values, Vt, NK, V,
        0LL, (long long)NK * V, (long long)O * NK);

    // K1: P = exp(scale * Qh @ Kh^T) (masked -> 0), row sums -> RS
    gemm_cp1<<<dim3(NK / BN, NQ / BM, B), 128, SMEM_CP>>>(
        Qh, Kh, S, NK, D,
        (long long)NQ * D, (long long)NK * D, (long long)NQ * NK,
        mask, (long long)NQ * NK, RS, scale);

    // K3: out = (P @ Vt^T) / rowsum + bias   (fp16 in, fp32 out)
    gemm_h16<<<dim3(O / BN, NQ / BM, B), 128, SMEM_DB>>>(
        S, Vt, out, O, NK,
        (long long)NQ * NK, (long long)O * NK, (long long)NQ * O,
        bias, RS);
}

// round 12
// speedup vs baseline: 1.0741x; 1.0053x over previous
#include <cuda_runtime.h>
#include <cuda_fp16.h>
#include <stdint.h>

// ---------------- scratch (alloc-free: __device__ globals) ----------------
__device__ __half g_S [16u * 1024u * 2048u];   // exp(logits), unnormalized  [B,NQ,NK] fp16
__device__ __half g_Vt[16u * 256u  * 2048u];   // V'^T = W @ V^T  [B,O,NK]   fp16
__device__ __half g_Qh[16u * 1024u * 512u];    // queries fp16
__device__ __half g_Kh[16u * 2048u * 512u];    // keys fp16
__device__ float  g_rsum[16u * 1024u];         // per-row sum of exp(logits)

// ---------------- helpers ----------------
__device__ __forceinline__ uint32_t smem_u32(const void* p) {
    uint32_t a;
    asm("{ .reg .u64 t; cvta.to.shared.u64 t, %1; cvt.u32.u64 %0, t; }" : "=r"(a) : "l"(p));
    return a;
}
__device__ __forceinline__ uint32_t f16x2(float lo, float hi) {
    uint32_t u;
    asm("cvt.rn.f16x2.f32 %0, %1, %2;" : "=r"(u) : "f"(hi), "f"(lo));
    return u;
}
__device__ __forceinline__ void mma_f16(float c[4], const uint32_t a[4], const uint32_t b[2]) {
    asm volatile(
        "mma.sync.aligned.m16n8k16.row.col.f32.f16.f16.f32 "
        "{%0,%1,%2,%3}, {%4,%5,%6,%7}, {%8,%9}, {%0,%1,%2,%3};"
        : "+f"(c[0]), "+f"(c[1]), "+f"(c[2]), "+f"(c[3])
        : "r"(a[0]), "r"(a[1]), "r"(a[2]), "r"(a[3]), "r"(b[0]), "r"(b[1]));
}
__device__ __forceinline__ void ldsm4(uint32_t& r0, uint32_t& r1, uint32_t& r2, uint32_t& r3,
                                      uint32_t addr) {
    asm volatile("ldmatrix.sync.aligned.m8n8.x4.shared.b16 {%0,%1,%2,%3}, [%4];"
                 : "=r"(r0), "=r"(r1), "=r"(r2), "=r"(r3) : "r"(addr));
}
__device__ __forceinline__ void sts64(uint32_t a, uint32_t x, uint32_t y) {
    asm volatile("st.shared.v2.b32 [%0], {%1,%2};" :: "r"(a), "r"(x), "r"(y) : "memory");
}
__device__ __forceinline__ void sts128(uint32_t a, uint4 v) {
    asm volatile("st.shared.v4.b32 [%0], {%1,%2,%3,%4};"
                 :: "r"(a), "r"(v.x), "r"(v.y), "r"(v.z), "r"(v.w) : "memory");
}
__device__ __forceinline__ void cpasync16(uint32_t dst, const void* src) {
    asm volatile("cp.async.cg.shared.global [%0], [%1], 16;" :: "r"(dst), "l"(src) : "memory");
}
#define CP_COMMIT() asm volatile("cp.async.commit_group;" ::: "memory")
#define CP_WAIT2()  asm volatile("cp.async.wait_group 2;" ::: "memory")

// ---------------- tiling ----------------
// CTA tile 128x128x32, 4 warps as 2(M) x 2(N), warp tile 64x64. 128 threads.
// Two CTAs/SM. fp16 smem rows: 64B data, stride 80B (conflict-free ldmatrix).
constexpr int BM = 128, BN = 128, BK = 32;
constexpr int SBH   = 80;                   // bytes per smem row
constexpr int A_B   = BM * SBH;             // 10240
constexpr int STG_B = (BM + BN) * SBH;      // 20480 per stage
constexpr int NSTG  = 4;
constexpr int SMEM_CP = NSTG * STG_B;       // 81920 (cp.async K1)
constexpr int SMEM_DB = 2 * STG_B;          // 40960 (double-buffered kernels)

// ======= fused fp32 -> fp16 convert for Q and K + zero row_sum =============
__global__ __launch_bounds__(256)
void cvt2_f2h(const float4* __restrict__ srcQ, uint2* __restrict__ dstQ, int n4q,
              const float4* __restrict__ srcK, uint2* __restrict__ dstK, int n4k,
              float4* __restrict__ rs4, int nrs4)
{
    const int gid = blockIdx.x * 256 + threadIdx.x;
    if (gid < nrs4) rs4[gid] = make_float4(0.f, 0.f, 0.f, 0.f);
    const int total = n4q + n4k;
    for (int i = gid; i < total; i += gridDim.x * 256) {
        const float4* s;
        uint2* d;
        int j;
        if (i < n4q) { s = srcQ; d = dstQ; j = i; }
        else         { s = srcK; d = dstK; j = i - n4q; }
        float4 v = s[j];
        uint2 o;
        o.x = f16x2(v.x, v.y);
        o.y = f16x2(v.z, v.w);
        d[j] = o;
    }
}

// ===================== K1: fp16 in, cp.async 4-stage =======================
// Writes P = exp(scale * (Q.K)) (masked -> 0) in fp16, and accumulates
// per-row sums of P into rsum via atomics (no separate softmax kernel).
__global__ __launch_bounds__(128, 2)
void gemm_cp1(const __half* __restrict__ Ag, const __half* __restrict__ Bg,
              __half* __restrict__ Cg, int N, int K,
              long long sA, long long sB, long long sC,
              const int* __restrict__ maskg, long long sMask,
              float* __restrict__ rsum, float scale)
{
    extern __shared__ char smem[];

    const int tid  = threadIdx.x;
    const int lane = tid & 31;
    const int warp = tid >> 5;
    const int wm = (warp & 1) * 64;
    const int wn = (warp >> 1) * 64;
    const int z  = blockIdx.z;
    const int m0 = blockIdx.y * BM;
    const int n0 = blockIdx.x * BN;

    const __half* A = Ag + (size_t)z * sA;
    const __half* B = Bg + (size_t)z * sB;

    const uint32_t sbase = smem_u32(smem);
    const uint32_t aRowB = (uint32_t)(wm + (lane & 15)) * SBH + (uint32_t)(lane >> 4) * 16;
    const uint32_t bRowB = (uint32_t)(wn + (lane & 7) + ((lane >> 4) << 3)) * SBH
                         + (uint32_t)((lane >> 3) & 1) * 16;
    const int KT = K / BK;

    // one chunk = 8 cp.async x 16B per thread (A 4, B 4)
    const int r4 = tid >> 2;               // 0..31 base row
    const int sg = (tid & 3) * 16;         // 16B segment within 64B row
    auto issue_chunk = [&](int c) {
        const uint32_t st = sbase + (uint32_t)(c & (NSTG - 1)) * STG_B;
        const int koff = c * BK + (tid & 3) * 8;
#pragma unroll
        for (int i = 0; i < 4; i++) {
            int r = r4 + 32 * i;
            cpasync16(st + (uint32_t)r * SBH + sg, A + (size_t)(m0 + r) * K + koff);
        }
#pragma unroll
        for (int i = 0; i < 4; i++) {
            int r = r4 + 32 * i;
            cpasync16(st + (uint32_t)A_B + (uint32_t)r * SBH + sg,
                      B + (size_t)(n0 + r) * K + koff);
        }
    };

    float acc[4][8][4];
#pragma unroll
    for (int i = 0; i < 4; i++)
#pragma unroll
        for (int j = 0; j < 8; j++)
#pragma unroll
            for (int r = 0; r < 4; r++) acc[i][j][r] = 0.0f;

    issue_chunk(0); CP_COMMIT();
    issue_chunk(1); CP_COMMIT();
    issue_chunk(2); CP_COMMIT();

    for (int kb = 0; kb < KT; ++kb) {
        CP_WAIT2();
        __syncthreads();
        if (kb + 3 < KT) issue_chunk(kb + 3);
        CP_COMMIT();

        const uint32_t curBase = sbase + (uint32_t)(kb & (NSTG - 1)) * STG_B;
        const uint32_t aB = curBase + aRowB;
        const uint32_t bB = curBase + (uint32_t)A_B + bRowB;

#pragma unroll
        for (int ks = 0; ks < 2; ++ks) {
            const uint32_t kB = (uint32_t)ks * 32;
            uint32_t af[4][4], bf[8][2];
#pragma unroll
            for (int mi = 0; mi < 4; mi++)
                ldsm4(af[mi][0], af[mi][1], af[mi][2], af[mi][3],
                      aB + (uint32_t)mi * (16 * SBH) + kB);
#pragma unroll
            for (int pr = 0; pr < 4; pr++)
                ldsm4(bf[2 * pr][0], bf[2 * pr][1], bf[2 * pr + 1][0], bf[2 * pr + 1][1],
                      bB + (uint32_t)pr * (16 * SBH) + kB);
#pragma unroll
            for (int mi = 0; mi < 4; mi++)
#pragma unroll
                for (int ni = 0; ni < 8; ni++)
                    mma_f16(acc[mi][ni], af[mi], bf[ni]);
        }
        __syncthreads();
    }

    // ---- epilogue: exp + mask -> store P, reduce row partial sums ----
    __half* C = Cg + (size_t)z * sC;
    const int* Mk = maskg + (size_t)z * sMask;
    float* RS = rsum + (size_t)z * 1024;

#pragma unroll
    for (int mi = 0; mi < 4; mi++) {
        const int row0 = m0 + wm + mi * 16 + (lane >> 2);
        float psum[2] = {0.0f, 0.0f};
#pragma unroll
        for (int ni = 0; ni < 8; ni++) {
            const int col = n0 + wn + ni * 8 + (lane & 3) * 2;
#pragma unroll
            for (int h = 0; h < 2; ++h) {
                const int row = row0 + h * 8;
                int2 mk = *(const int2*)(Mk + (size_t)row * N + col);
                float v0 = mk.x ? __expf(acc[mi][ni][2 * h] * scale)     : 0.0f;
                float v1 = mk.y ? __expf(acc[mi][ni][2 * h + 1] * scale) : 0.0f;
                psum[h] += v0 + v1;
                *(__half2*)(C + (size_t)row * N + col) = __floats2half2_rn(v0, v1);
            }
        }
#pragma unroll
        for (int h = 0; h < 2; ++h) {
            float s = psum[h];
            s += __shfl_xor_sync(0xffffffffu, s, 1);
            s += __shfl_xor_sync(0xffffffffu, s, 2);
            if ((lane & 3) == 0) atomicAdd(RS + row0 + h * 8, s);
        }
    }
}

// ===================== K3: fp16 in -> fp32 out, scale by 1/rowsum + bias ===
__global__ __launch_bounds__(128, 2)
void gemm_h16(const __half* __restrict__ Ag, const __half* __restrict__ Bg,
              float* __restrict__ Cg, int N, int K,
              long long sA, long long sB, long long sC,
              const float* __restrict__ bias, const float* __restrict__ rsum)
{
    extern __shared__ char smem[];

    const int tid  = threadIdx.x;
    const int lane = tid & 31;
    const int warp = tid >> 5;
    const int wm = (warp & 1) * 64;
    const int wn = (warp >> 1) * 64;
    const int z  = blockIdx.z;
    const int m0 = blockIdx.y * BM;
    const int n0 = blockIdx.x * BN;

    const __half* A = Ag + (size_t)z * sA;
    const __half* B = Bg + (size_t)z * sB;

    const uint32_t sbase = smem_u32(smem);
    const uint32_t aRowB = (uint32_t)(wm + (lane & 15)) * SBH + (uint32_t)(lane >> 4) * 16;
    const uint32_t bRowB = (uint32_t)(wn + (lane & 7) + ((lane >> 4) << 3)) * SBH
                         + (uint32_t)((lane >> 3) & 1) * 16;
    const int KT = K / BK;

    uint4 ra[4], rb[4];
    auto load_regs = [&](int c) {
        const int koff = c * BK;
#pragma unroll
        for (int i = 0; i < 4; i++) {
            int f = tid + 128 * i, r = f >> 2, sg = f & 3;
            ra[i] = *(const uint4*)(A + (size_t)(m0 + r) * K + koff + sg * 8);
        }
#pragma unroll
        for (int i = 0; i < 4; i++) {
            int f = tid + 128 * i, r = f >> 2, sg = f & 3;
            rb[i] = *(const uint4*)(B + (size_t)(n0 + r) * K + koff + sg * 8);
        }
    };
    auto store_stage = [&](int s) {
        const uint32_t st = sbase + (uint32_t)s * STG_B;
#pragma unroll
        for (int i = 0; i < 4; i++) {
            int f = tid + 128 * i, r = f >> 2, sg = f & 3;
            sts128(st + (uint32_t)r * SBH + (uint32_t)sg * 16, ra[i]);
        }
#pragma unroll
        for (int i = 0; i < 4; i++) {
            int f = tid + 128 * i, r = f >> 2, sg = f & 3;
            sts128(st + (uint32_t)A_B + (uint32_t)r * SBH + (uint32_t)sg * 16, rb[i]);
        }
    };

    float acc[4][8][4];
#pragma unroll
    for (int i = 0; i < 4; i++)
#pragma unroll
        for (int j = 0; j < 8; j++)
#pragma unroll
            for (int r = 0; r < 4; r++) acc[i][j][r] = 0.0f;

    load_regs(0);
    store_stage(0);
    __syncthreads();
    if (KT > 1) load_regs(1);

    for (int kb = 0; kb < KT; ++kb) {
        const int cur = kb & 1;
        if (kb + 1 < KT) store_stage(cur ^ 1);
        if (kb + 2 < KT) load_regs(kb + 2);

        const uint32_t curBase = sbase + (uint32_t)cur * STG_B;
        const uint32_t aB = curBase + aRowB;
        const uint32_t bB = curBase + (uint32_t)A_B + bRowB;

#pragma unroll
        for (int ks = 0; ks < 2; ++ks) {
            const uint32_t kB = (uint32_t)ks * 32;
            uint32_t af[4][4], bf[8][2];
#pragma unroll
            for (int mi = 0; mi < 4; mi++)
                ldsm4(af[mi][0], af[mi][1], af[mi][2], af[mi][3],
                      aB + (uint32_t)mi * (16 * SBH) + kB);
#pragma unroll
            for (int pr = 0; pr < 4; pr++)
                ldsm4(bf[2 * pr][0], bf[2 * pr][1], bf[2 * pr + 1][0], bf[2 * pr + 1][1],
                      bB + (uint32_t)pr * (16 * SBH) + kB);
#pragma unroll
            for (int mi = 0; mi < 4; mi++)
#pragma unroll
                for (int ni = 0; ni < 8; ni++)
                    mma_f16(acc[mi][ni], af[mi], bf[ni]);
        }
        __syncthreads();
    }

    float* C = Cg + (size_t)z * sC;
    const float* RS = rsum + (size_t)z * 1024;
#pragma unroll
    for (int mi = 0; mi < 4; mi++) {
        const int row0 = m0 + wm + mi * 16 + (lane >> 2);
        const float inv0 = 1.0f / RS[row0];
        const float inv1 = 1.0f / RS[row0 + 8];
#pragma unroll
        for (int ni = 0; ni < 8; ni++) {
            const int col = n0 + wn + ni * 8 + (lane & 3) * 2;
            const float b0 = bias[col], b1 = bias[col + 1];
            float2 o;
            o.x = acc[mi][ni][0] * inv0 + b0;
            o.y = acc[mi][ni][1] * inv0 + b1;
            *(float2*)(C + (size_t)row0 * N + col) = o;
            o.x = acc[mi][ni][2] * inv1 + b0;
            o.y = acc[mi][ni][3] * inv1 + b1;
            *(float2*)(C + (size_t)(row0 + 8) * N + col) = o;
        }
    }
}

// ===================== K0: fp32 inputs -> fp16 out =========================
__global__ __launch_bounds__(128, 2)
void gemm_a32(const float* __restrict__ Ag, const float* __restrict__ Bg,
              __half* __restrict__ Cg, int N, int K,
              long long sA, long long sB, long long sC)
{
    extern __shared__ char smem[];

    const int tid  = threadIdx.x;
    const int lane = tid & 31;
    const int warp = tid >> 5;
    const int wm = (warp & 1) * 64;
    const int wn = (warp >> 1) * 64;
    const int z  = blockIdx.z;
    const int m0 = blockIdx.y * BM;
    const int n0 = blockIdx.x * BN;

    const float* A = Ag + (size_t)z * sA;
    const float* B = Bg + (size_t)z * sB;

    const uint32_t sbase = smem_u32(smem);
    const uint32_t aRowB = (uint32_t)(wm + (lane & 15)) * SBH + (uint32_t)(lane >> 4) * 16;
    const uint32_t bRowB = (uint32_t)(wn + (lane & 7) + ((lane >> 4) << 3)) * SBH
                         + (uint32_t)((lane >> 3) & 1) * 16;
    const int KT = K / BK;

    float4 ra[8], rb[8];
    auto load_regs = [&](int c) {
        const int koff = c * BK;
#pragma unroll
        for (int i = 0; i < 8; i++) {
            int f = tid + 128 * i, r = f >> 3, q = (f & 7) * 4;
            ra[i] = *(const float4*)(A + (size_t)(m0 + r) * K + koff + q);
        }
#pragma unroll
        for (int i = 0; i < 8; i++) {
            int f = tid + 128 * i, r = f >> 3, q = (f & 7) * 4;
            rb[i] = *(const float4*)(B + (size_t)(n0 + r) * K + koff + q);
        }
    };
    auto store_stage = [&](int s) {
        const uint32_t st = sbase + (uint32_t)s * STG_B;
#pragma unroll
        for (int i = 0; i < 8; i++) {
            int f = tid + 128 * i, r = f >> 3, q = (f & 7) * 4;
            sts64(st + (uint32_t)r * SBH + (uint32_t)q * 2,
                  f16x2(ra[i].x, ra[i].y), f16x2(ra[i].z, ra[i].w));
        }
#pragma unroll
        for (int i = 0; i < 8; i++) {
            int f = tid + 128 * i, r = f >> 3, q = (f & 7) * 4;
            sts64(st + (uint32_t)A_B + (uint32_t)r * SBH + (uint32_t)q * 2,
                  f16x2(rb[i].x, rb[i].y), f16x2(rb[i].z, rb[i].w));
        }
    };

    float acc[4][8][4];
#pragma unroll
    for (int i = 0; i < 4; i++)
#pragma unroll
        for (int j = 0; j < 8; j++)
#pragma unroll
            for (int r = 0; r < 4; r++) acc[i][j][r] = 0.0f;

    load_regs(0);
    store_stage(0);
    __syncthreads();
    if (KT > 1) load_regs(1);

    for (int kb = 0; kb < KT; ++kb) {
        const int cur = kb & 1;
        if (kb + 1 < KT) store_stage(cur ^ 1);
        if (kb + 2 < KT) load_regs(kb + 2);

        const uint32_t curBase = sbase + (uint32_t)cur * STG_B;
        const uint32_t aB = curBase + aRowB;
        const uint32_t bB = curBase + (uint32_t)A_B + bRowB;

#pragma unroll
        for (int ks = 0; ks < 2; ++ks) {
            const uint32_t kB = (uint32_t)ks * 32;
            uint32_t af[4][4], bf[8][2];
#pragma unroll
            for (int mi = 0; mi < 4; mi++)
                ldsm4(af[mi][0], af[mi][1], af[mi][2], af[mi][3],
                      aB + (uint32_t)mi * (16 * SBH) + kB);
#pragma unroll
            for (int pr = 0; pr < 4; pr++)
                ldsm4(bf[2 * pr][0], bf[2 * pr][1], bf[2 * pr + 1][0], bf[2 * pr + 1][1],
                      bB + (uint32_t)pr * (16 * SBH) + kB);
#pragma unroll
            for (int mi = 0; mi < 4; mi++)
#pragma unroll
                for (int ni = 0; ni < 8; ni++)
                    mma_f16(acc[mi][ni], af[mi], bf[ni]);
        }
        __syncthreads();
    }

    __half* C = Cg + (size_t)z * sC;
#pragma unroll
    for (int mi = 0; mi < 4; mi++) {
#pragma unroll
        for (int ni = 0; ni < 8; ni++) {
            const int row0 = m0 + wm + mi * 16 + (lane >> 2);
            const int col  = n0 + wn + ni * 8 + (lane & 3) * 2;
#pragma unroll
            for (int h = 0; h < 2; ++h) {
                const int row = row0 + h * 8;
                *(__half2*)(C + (size_t)row * N + col) =
                    __floats2half2_rn(acc[mi][ni][2 * h], acc[mi][ni][2 * h + 1]);
            }
        }
    }
}

// ---------------- launch ----------------
extern "C" void kernel_launch(void* const* d_in, const int* in_sizes, int n_in,
                              void* d_out, int out_size)
{
    const float* keys    = (const float*)d_in[0];   // [16, 2048, 512]
    const float* queries = (const float*)d_in[1];   // [16, 1024, 512]
    const float* values  = (const float*)d_in[2];   // [16, 2048, 512]
    const int*   mask    = (const int*)  d_in[3];   // [16, 1024, 2048]
    const float* W       = (const float*)d_in[4];   // [256, 512]
    const float* bias    = (const float*)d_in[5];   // [256]
    float* out = (float*)d_out;                     // [16, 1024, 256]

    const int B = 16, NQ = 1024, NK = 2048, D = 512, V = 512, O = 256;
    const float scale = 1.0f / sqrtf(512.0f);       // KQ = 512

    __half *S, *Vt, *Qh, *Kh;
    float* RS;
    cudaGetSymbolAddress((void**)&S,  g_S);
    cudaGetSymbolAddress((void**)&Vt, g_Vt);
    cudaGetSymbolAddress((void**)&Qh, g_Qh);
    cudaGetSymbolAddress((void**)&Kh, g_Kh);
    cudaGetSymbolAddress((void**)&RS, g_rsum);

    cudaFuncSetAttribute(gemm_a32, cudaFuncAttributeMaxDynamicSharedMemorySize, SMEM_DB);
    cudaFuncSetAttribute(gemm_cp1, cudaFuncAttributeMaxDynamicSharedMemorySize, SMEM_CP);
    cudaFuncSetAttribute(gemm_h16, cudaFuncAttributeMaxDynamicSharedMemorySize, SMEM_DB);

    // Fork a side stream for K0 (independent of cvt/K1). Created per call and
    // intentionally not destroyed: kernel_launch runs only for correctness +
    // capture, and destroying a stream that participates in an active capture
    // would invalidate the graph. Host-side resources only — no device memory.
    cudaStream_t s2;
    cudaStreamCreateWithFlags(&s2, cudaStreamNonBlocking);
    cudaEvent_t eFork, eJoin;
    cudaEventCreateWithFlags(&eFork, cudaEventDisableTiming);
    cudaEventCreateWithFlags(&eJoin, cudaEventDisableTiming);

    // Fork: s2 joins the capture DAG after the current point on stream 0.
    cudaEventRecord(eFork, 0);
    cudaStreamWaitEvent(s2, eFork, 0);

    // K0 on s2: Vt[b][o][n] = sum_v W[o][v] * values[b][n][v]  (fp32 in, fp16 out)
    gemm_a32<<<dim3(NK / BN, O / BM, B), 128, SMEM_DB, s2>>>(
        W, values, Vt, NK, V,
        0LL, (long long)NK * V, (long long)O * NK);
    cudaEventRecord(eJoin, s2);

    // Main stream: convert Q and K to fp16 + zero row sums
    cvt2_f2h<<<888, 256>>>((const float4*)queries, (uint2*)Qh, B * NQ * D / 4,
                           (const float4*)keys,    (uint2*)Kh, B * NK * D / 4,
                           (float4*)RS, B * NQ / 4);

    // K1: P = exp(scale * Qh @ Kh^T) (masked -> 0), row sums -> RS
    gemm_cp1<<<dim3(NK / BN, NQ / BM, B), 128, SMEM_CP>>>(
        Qh, Kh, S, NK, D,
        (long long)NQ * D, (long long)NK * D, (long long)NQ * NK,
        mask, (long long)NQ * NK, RS, scale);

    // Join: K3 needs both K1 (stream 0) and K0 (s2).
    cudaStreamWaitEvent(0, eJoin, 0);

    // K3: out = (P @ Vt^T) / rowsum + bias   (fp16 in, fp32 out)
    gemm_h16<<<dim3(O / BN, NQ / BM, B), 128, SMEM_DB>>>(
        S, Vt, out, O, NK,
        (long long)NQ * NK, (long long)O * NK, (long long)NQ * O,
        bias, RS);
}

// round 14
// speedup vs baseline: 1.1079x; 1.0315x over previous
#include <cuda_runtime.h>
#include <cuda_fp16.h>
#include <stdint.h>

// ---------------- scratch (alloc-free: __device__ globals) ----------------
__device__ __half g_S [16u * 1024u * 2048u];   // exp(logits), unnormalized  [B,NQ,NK] fp16
__device__ __half g_Vt[16u * 256u  * 2048u];   // V'^T = W @ V^T  [B,O,NK]   fp16
__device__ float  g_rsum[16u * 1024u];         // per-row sum of exp(logits)

// ---------------- helpers ----------------
__device__ __forceinline__ uint32_t smem_u32(const void* p) {
    uint32_t a;
    asm("{ .reg .u64 t; cvta.to.shared.u64 t, %1; cvt.u32.u64 %0, t; }" : "=r"(a) : "l"(p));
    return a;
}
__device__ __forceinline__ uint32_t f16x2(float lo, float hi) {
    uint32_t u;
    asm("cvt.rn.f16x2.f32 %0, %1, %2;" : "=r"(u) : "f"(hi), "f"(lo));
    return u;
}
__device__ __forceinline__ void mma_f16(float c[4], const uint32_t a[4], const uint32_t b[2]) {
    asm volatile(
        "mma.sync.aligned.m16n8k16.row.col.f32.f16.f16.f32 "
        "{%0,%1,%2,%3}, {%4,%5,%6,%7}, {%8,%9}, {%0,%1,%2,%3};"
        : "+f"(c[0]), "+f"(c[1]), "+f"(c[2]), "+f"(c[3])
        : "r"(a[0]), "r"(a[1]), "r"(a[2]), "r"(a[3]), "r"(b[0]), "r"(b[1]));
}
__device__ __forceinline__ void ldsm4(uint32_t& r0, uint32_t& r1, uint32_t& r2, uint32_t& r3,
                                      uint32_t addr) {
    asm volatile("ldmatrix.sync.aligned.m8n8.x4.shared.b16 {%0,%1,%2,%3}, [%4];"
                 : "=r"(r0), "=r"(r1), "=r"(r2), "=r"(r3) : "r"(addr));
}
__device__ __forceinline__ void sts64(uint32_t a, uint32_t x, uint32_t y) {
    asm volatile("st.shared.v2.b32 [%0], {%1,%2};" :: "r"(a), "r"(x), "r"(y) : "memory");
}
__device__ __forceinline__ void sts128(uint32_t a, uint4 v) {
    asm volatile("st.shared.v4.b32 [%0], {%1,%2,%3,%4};"
                 :: "r"(a), "r"(v.x), "r"(v.y), "r"(v.z), "r"(v.w) : "memory");
}

// ---------------- tiling ----------------
// CTA tile 128x128x32, 4 warps as 2(M) x 2(N), warp tile 64x64. 128 threads.
// Two CTAs/SM. fp16 smem rows: 64B data, stride 80B (conflict-free ldmatrix).
constexpr int BM = 128, BN = 128, BK = 32;
constexpr int SBH   = 80;                   // bytes per smem row
constexpr int A_B   = BM * SBH;             // 10240
constexpr int STG_B = (BM + BN) * SBH;      // 20480 per stage
constexpr int SMEM_DB = 2 * STG_B;          // 40960 (double-buffered)

// ===================== zero row_sum =====================
__global__ __launch_bounds__(256)
void zero_rs(float4* __restrict__ rs4)
{
    rs4[blockIdx.x * 256 + threadIdx.x] = make_float4(0.f, 0.f, 0.f, 0.f);
}

// ===================== K1: fp32 inputs (in-kernel cvt), fused epilogue =====
// P[z][m][n] = exp(scale * sum_k Q[z][m][k]*Kk[z][n][k])  (mask==0 -> 0), fp16.
// Row sums of P accumulate into rsum via atomics.
__global__ __launch_bounds__(128, 2)
void gemm_k1(const float* __restrict__ Ag, const float* __restrict__ Bg,
             __half* __restrict__ Cg, int N, int K,
             long long sA, long long sB, long long sC,
             const int* __restrict__ maskg, long long sMask,
             float* __restrict__ rsum, float scale)
{
    extern __shared__ char smem[];

    const int tid  = threadIdx.x;
    const int lane = tid & 31;
    const int warp = tid >> 5;
    const int wm = (warp & 1) * 64;
    const int wn = (warp >> 1) * 64;
    const int z  = blockIdx.z;
    const int m0 = blockIdx.y * BM;
    const int n0 = blockIdx.x * BN;

    const float* A = Ag + (size_t)z * sA;
    const float* B = Bg + (size_t)z * sB;

    const uint32_t sbase = smem_u32(smem);
    const uint32_t aRowB = (uint32_t)(wm + (lane & 15)) * SBH + (uint32_t)(lane >> 4) * 16;
    const uint32_t bRowB = (uint32_t)(wn + (lane & 7) + ((lane >> 4) << 3)) * SBH
                         + (uint32_t)((lane >> 3) & 1) * 16;
    const int KT = K / BK;

    float4 ra[8], rb[8];
    auto load_regs = [&](int c) {
        const int koff = c * BK;
#pragma unroll
        for (int i = 0; i < 8; i++) {
            int f = tid + 128 * i, r = f >> 3, q = (f & 7) * 4;
            ra[i] = *(const float4*)(A + (size_t)(m0 + r) * K + koff + q);
        }
#pragma unroll
        for (int i = 0; i < 8; i++) {
            int f = tid + 128 * i, r = f >> 3, q = (f & 7) * 4;
            rb[i] = *(const float4*)(B + (size_t)(n0 + r) * K + koff + q);
        }
    };
    auto store_stage = [&](int s) {
        const uint32_t st = sbase + (uint32_t)s * STG_B;
#pragma unroll
        for (int i = 0; i < 8; i++) {
            int f = tid + 128 * i, r = f >> 3, q = (f & 7) * 4;
            sts64(st + (uint32_t)r * SBH + (uint32_t)q * 2,
                  f16x2(ra[i].x, ra[i].y), f16x2(ra[i].z, ra[i].w));
        }
#pragma unroll
        for (int i = 0; i < 8; i++) {
            int f = tid + 128 * i, r = f >> 3, q = (f & 7) * 4;
            sts64(st + (uint32_t)A_B + (uint32_t)r * SBH + (uint32_t)q * 2,
                  f16x2(rb[i].x, rb[i].y), f16x2(rb[i].z, rb[i].w));
        }
    };

    float acc[4][8][4];
#pragma unroll
    for (int i = 0; i < 4; i++)
#pragma unroll
        for (int j = 0; j < 8; j++)
#pragma unroll
            for (int r = 0; r < 4; r++) acc[i][j][r] = 0.0f;

    load_regs(0);
    store_stage(0);
    __syncthreads();
    if (KT > 1) load_regs(1);

    for (int kb = 0; kb < KT; ++kb) {
        const int cur = kb & 1;
        if (kb + 1 < KT) store_stage(cur ^ 1);
        if (kb + 2 < KT) load_regs(kb + 2);

        const uint32_t curBase = sbase + (uint32_t)cur * STG_B;
        const uint32_t aB = curBase + aRowB;
        const uint32_t bB = curBase + (uint32_t)A_B + bRowB;

#pragma unroll
        for (int ks = 0; ks < 2; ++ks) {
            const uint32_t kB = (uint32_t)ks * 32;
            uint32_t af[4][4], bf[8][2];
#pragma unroll
            for (int mi = 0; mi < 4; mi++)
                ldsm4(af[mi][0], af[mi][1], af[mi][2], af[mi][3],
                      aB + (uint32_t)mi * (16 * SBH) + kB);
#pragma unroll
            for (int pr = 0; pr < 4; pr++)
                ldsm4(bf[2 * pr][0], bf[2 * pr][1], bf[2 * pr + 1][0], bf[2 * pr + 1][1],
                      bB + (uint32_t)pr * (16 * SBH) + kB);
#pragma unroll
            for (int mi = 0; mi < 4; mi++)
#pragma unroll
                for (int ni = 0; ni < 8; ni++)
                    mma_f16(acc[mi][ni], af[mi], bf[ni]);
        }
        __syncthreads();
    }

    // ---- fused epilogue: exp + mask -> store P, reduce row partial sums ----
    __half* C = Cg + (size_t)z * sC;
    const int* Mk = maskg + (size_t)z * sMask;
    float* RS = rsum + (size_t)z * 1024;

#pragma unroll
    for (int mi = 0; mi < 4; mi++) {
        const int row0 = m0 + wm + mi * 16 + (lane >> 2);
        float psum[2] = {0.0f, 0.0f};
#pragma unroll
        for (int ni = 0; ni < 8; ni++) {
            const int col = n0 + wn + ni * 8 + (lane & 3) * 2;
#pragma unroll
            for (int h = 0; h < 2; ++h) {
                const int row = row0 + h * 8;
                int2 mk = *(const int2*)(Mk + (size_t)row * N + col);
                float v0 = mk.x ? __expf(acc[mi][ni][2 * h] * scale)     : 0.0f;
                float v1 = mk.y ? __expf(acc[mi][ni][2 * h + 1] * scale) : 0.0f;
                psum[h] += v0 + v1;
                *(__half2*)(C + (size_t)row * N + col) = __floats2half2_rn(v0, v1);
            }
        }
#pragma unroll
        for (int h = 0; h < 2; ++h) {
            float s = psum[h];
            s += __shfl_xor_sync(0xffffffffu, s, 1);
            s += __shfl_xor_sync(0xffffffffu, s, 2);
            if ((lane & 3) == 0) atomicAdd(RS + row0 + h * 8, s);
        }
    }
}

// ===================== K3: fp16 in -> fp32 out, scale by 1/rowsum + bias ===
__global__ __launch_bounds__(128, 2)
void gemm_h16(const __half* __restrict__ Ag, const __half* __restrict__ Bg,
              float* __restrict__ Cg, int N, int K,
              long long sA, long long sB, long long sC,
              const float* __restrict__ bias, const float* __restrict__ rsum)
{
    extern __shared__ char smem[];

    const int tid  = threadIdx.x;
    const int lane = tid & 31;
    const int warp = tid >> 5;
    const int wm = (warp & 1) * 64;
    const int wn = (warp >> 1) * 64;
    const int z  = blockIdx.z;
    const int m0 = blockIdx.y * BM;
    const int n0 = blockIdx.x * BN;

    const __half* A = Ag + (size_t)z * sA;
    const __half* B = Bg + (size_t)z * sB;

    const uint32_t sbase = smem_u32(smem);
    const uint32_t aRowB = (uint32_t)(wm + (lane & 15)) * SBH + (uint32_t)(lane >> 4) * 16;
    const uint32_t bRowB = (uint32_t)(wn + (lane & 7) + ((lane >> 4) << 3)) * SBH
                         + (uint32_t)((lane >> 3) & 1) * 16;
    const int KT = K / BK;

    uint4 ra[4], rb[4];
    auto load_regs = [&](int c) {
        const int koff = c * BK;
#pragma unroll
        for (int i = 0; i < 4; i++) {
            int f = tid + 128 * i, r = f >> 2, sg = f & 3;
            ra[i] = *(const uint4*)(A + (size_t)(m0 + r) * K + koff + sg * 8);
        }
#pragma unroll
        for (int i = 0; i < 4; i++) {
            int f = tid + 128 * i, r = f >> 2, sg = f & 3;
            rb[i] = *(const uint4*)(B + (size_t)(n0 + r) * K + koff + sg * 8);
        }
    };
    auto store_stage = [&](int s) {
        const uint32_t st = sbase + (uint32_t)s * STG_B;
#pragma unroll
        for (int i = 0; i < 4; i++) {
            int f = tid + 128 * i, r = f >> 2, sg = f & 3;
            sts128(st + (uint32_t)r * SBH + (uint32_t)sg * 16, ra[i]);
        }
#pragma unroll
        for (int i = 0; i < 4; i++) {
            int f = tid + 128 * i, r = f >> 2, sg = f & 3;
            sts128(st + (uint32_t)A_B + (uint32_t)r * SBH + (uint32_t)sg * 16, rb[i]);
        }
    };

    float acc[4][8][4];
#pragma unroll
    for (int i = 0; i < 4; i++)
#pragma unroll
        for (int j = 0; j < 8; j++)
#pragma unroll
            for (int r = 0; r < 4; r++) acc[i][j][r] = 0.0f;

    load_regs(0);
    store_stage(0);
    __syncthreads();
    if (KT > 1) load_regs(1);

    for (int kb = 0; kb < KT; ++kb) {
        const int cur = kb & 1;
        if (kb + 1 < KT) store_stage(cur ^ 1);
        if (kb + 2 < KT) load_regs(kb + 2);

        const uint32_t curBase = sbase + (uint32_t)cur * STG_B;
        const uint32_t aB = curBase + aRowB;
        const uint32_t bB = curBase + (uint32_t)A_B + bRowB;

#pragma unroll
        for (int ks = 0; ks < 2; ++ks) {
            const uint32_t kB = (uint32_t)ks * 32;
            uint32_t af[4][4], bf[8][2];
#pragma unroll
            for (int mi = 0; mi < 4; mi++)
                ldsm4(af[mi][0], af[mi][1], af[mi][2], af[mi][3],
                      aB + (uint32_t)mi * (16 * SBH) + kB);
#pragma unroll
            for (int pr = 0; pr < 4; pr++)
                ldsm4(bf[2 * pr][0], bf[2 * pr][1], bf[2 * pr + 1][0], bf[2 * pr + 1][1],
                      bB + (uint32_t)pr * (16 * SBH) + kB);
#pragma unroll
            for (int mi = 0; mi < 4; mi++)
#pragma unroll
                for (int ni = 0; ni < 8; ni++)
                    mma_f16(acc[mi][ni], af[mi], bf[ni]);
        }
        __syncthreads();
    }

    float* C = Cg + (size_t)z * sC;
    const float* RS = rsum + (size_t)z * 1024;
#pragma unroll
    for (int mi = 0; mi < 4; mi++) {
        const int row0 = m0 + wm + mi * 16 + (lane >> 2);
        const float inv0 = 1.0f / RS[row0];
        const float inv1 = 1.0f / RS[row0 + 8];
#pragma unroll
        for (int ni = 0; ni < 8; ni++) {
            const int col = n0 + wn + ni * 8 + (lane & 3) * 2;
            const float b0 = bias[col], b1 = bias[col + 1];
            float2 o;
            o.x = acc[mi][ni][0] * inv0 + b0;
            o.y = acc[mi][ni][1] * inv0 + b1;
            *(float2*)(C + (size_t)row0 * N + col) = o;
            o.x = acc[mi][ni][2] * inv1 + b0;
            o.y = acc[mi][ni][3] * inv1 + b1;
            *(float2*)(C + (size_t)(row0 + 8) * N + col) = o;
        }
    }
}

// ===================== K0: fp32 inputs -> fp16 out =========================
__global__ __launch_bounds__(128, 2)
void gemm_a32(const float* __restrict__ Ag, const float* __restrict__ Bg,
              __half* __restrict__ Cg, int N, int K,
              long long sA, long long sB, long long sC)
{
    extern __shared__ char smem[];

    const int tid  = threadIdx.x;
    const int lane = tid & 31;
    const int warp = tid >> 5;
    const int wm = (warp & 1) * 64;
    const int wn = (warp >> 1) * 64;
    const int z  = blockIdx.z;
    const int m0 = blockIdx.y * BM;
    const int n0 = blockIdx.x * BN;

    const float* A = Ag + (size_t)z * sA;
    const float* B = Bg + (size_t)z * sB;

    const uint32_t sbase = smem_u32(smem);
    const uint32_t aRowB = (uint32_t)(wm + (lane & 15)) * SBH + (uint32_t)(lane >> 4) * 16;
    const uint32_t bRowB = (uint32_t)(wn + (lane & 7) + ((lane >> 4) << 3)) * SBH
                         + (uint32_t)((lane >> 3) & 1) * 16;
    const int KT = K / BK;

    float4 ra[8], rb[8];
    auto load_regs = [&](int c) {
        const int koff = c * BK;
#pragma unroll
        for (int i = 0; i < 8; i++) {
            int f = tid + 128 * i, r = f >> 3, q = (f & 7) * 4;
            ra[i] = *(const float4*)(A + (size_t)(m0 + r) * K + koff + q);
        }
#pragma unroll
        for (int i = 0; i < 8; i++) {
            int f = tid + 128 * i, r = f >> 3, q = (f & 7) * 4;
            rb[i] = *(const float4*)(B + (size_t)(n0 + r) * K + koff + q);
        }
    };
    auto store_stage = [&](int s) {
        const uint32_t st = sbase + (uint32_t)s * STG_B;
#pragma unroll
        for (int i = 0; i < 8; i++) {
            int f = tid + 128 * i, r = f >> 3, q = (f & 7) * 4;
            sts64(st + (uint32_t)r * SBH + (uint32_t)q * 2,
                  f16x2(ra[i].x, ra[i].y), f16x2(ra[i].z, ra[i].w));
        }
#pragma unroll
        for (int i = 0; i < 8; i++) {
            int f = tid + 128 * i, r = f >> 3, q = (f & 7) * 4;
            sts64(st + (uint32_t)A_B + (uint32_t)r * SBH + (uint32_t)q * 2,
                  f16x2(rb[i].x, rb[i].y), f16x2(rb[i].z, rb[i].w));
        }
    };

    float acc[4][8][4];
#pragma unroll
    for (int i = 0; i < 4; i++)
#pragma unroll
        for (int j = 0; j < 8; j++)
#pragma unroll
            for (int r = 0; r < 4; r++) acc[i][j][r] = 0.0f;

    load_regs(0);
    store_stage(0);
    __syncthreads();
    if (KT > 1) load_regs(1);

    for (int kb = 0; kb < KT; ++kb) {
        const int cur = kb & 1;
        if (kb + 1 < KT) store_stage(cur ^ 1);
        if (kb + 2 < KT) load_regs(kb + 2);

        const uint32_t curBase = sbase + (uint32_t)cur * STG_B;
        const uint32_t aB = curBase + aRowB;
        const uint32_t bB = curBase + (uint32_t)A_B + bRowB;

#pragma unroll
        for (int ks = 0; ks < 2; ++ks) {
            const uint32_t kB = (uint32_t)ks * 32;
            uint32_t af[4][4], bf[8][2];
#pragma unroll
            for (int mi = 0; mi < 4; mi++)
                ldsm4(af[mi][0], af[mi][1], af[mi][2], af[mi][3],
                      aB + (uint32_t)mi * (16 * SBH) + kB);
#pragma unroll
            for (int pr = 0; pr < 4; pr++)
                ldsm4(bf[2 * pr][0], bf[2 * pr][1], bf[2 * pr + 1][0], bf[2 * pr + 1][1],
                      bB + (uint32_t)pr * (16 * SBH) + kB);
#pragma unroll
            for (int mi = 0; mi < 4; mi++)
#pragma unroll
                for (int ni = 0; ni < 8; ni++)
                    mma_f16(acc[mi][ni], af[mi], bf[ni]);
        }
        __syncthreads();
    }

    __half* C = Cg + (size_t)z * sC;
#pragma unroll
    for (int mi = 0; mi < 4; mi++) {
#pragma unroll
        for (int ni = 0; ni < 8; ni++) {
            const int row0 = m0 + wm + mi * 16 + (lane >> 2);
            const int col  = n0 + wn + ni * 8 + (lane & 3) * 2;
#pragma unroll
            for (int h = 0; h < 2; ++h) {
                const int row = row0 + h * 8;
                *(__half2*)(C + (size_t)row * N + col) =
                    __floats2half2_rn(acc[mi][ni][2 * h], acc[mi][ni][2 * h + 1]);
            }
        }
    }
}

// ---------------- launch ----------------
extern "C" void kernel_launch(void* const* d_in, const int* in_sizes, int n_in,
                              void* d_out, int out_size)
{
    const float* keys    = (const float*)d_in[0];   // [16, 2048, 512]
    const float* queries = (const float*)d_in[1];   // [16, 1024, 512]
    const float* values  = (const float*)d_in[2];   // [16, 2048, 512]
    const int*   mask    = (const int*)  d_in[3];   // [16, 1024, 2048]
    const float* W       = (const float*)d_in[4];   // [256, 512]
    const float* bias    = (const float*)d_in[5];   // [256]
    float* out = (float*)d_out;                     // [16, 1024, 256]

    const int B = 16, NQ = 1024, NK = 2048, D = 512, V = 512, O = 256;
    const float scale = 1.0f / sqrtf(512.0f);       // KQ = 512

    __half *S, *Vt;
    float* RS;
    cudaGetSymbolAddress((void**)&S,  g_S);
    cudaGetSymbolAddress((void**)&Vt, g_Vt);
    cudaGetSymbolAddress((void**)&RS, g_rsum);

    cudaFuncSetAttribute(gemm_a32, cudaFuncAttributeMaxDynamicSharedMemorySize, SMEM_DB);
    cudaFuncSetAttribute(gemm_k1,  cudaFuncAttributeMaxDynamicSharedMemorySize, SMEM_DB);
    cudaFuncSetAttribute(gemm_h16, cudaFuncAttributeMaxDynamicSharedMemorySize, SMEM_DB);

    // Fork a side stream for K0 (independent of K1). Host-side resources only;
    // intentionally not destroyed (kernel_launch runs twice: correctness +
    // capture; destroying mid-capture would invalidate the graph).
    cudaStream_t s2;
    cudaStreamCreateWithFlags(&s2, cudaStreamNonBlocking);
    cudaEvent_t eFork, eJoin;
    cudaEventCreateWithFlags(&eFork, cudaEventDisableTiming);
    cudaEventCreateWithFlags(&eJoin, cudaEventDisableTiming);

    cudaEventRecord(eFork, 0);
    cudaStreamWaitEvent(s2, eFork, 0);

    // K0 on s2: Vt[b][o][n] = sum_v W[o][v] * values[b][n][v]  (fp32 in, fp16 out)
    gemm_a32<<<dim3(NK / BN, O / BM, B), 128, SMEM_DB, s2>>>(
        W, values, Vt, NK, V,
        0LL, (long long)NK * V, (long long)O * NK);
    cudaEventRecord(eJoin, s2);

    // Main stream: zero row sums (tiny), then K1.
    zero_rs<<<16, 256>>>((float4*)RS);

    // K1: P = exp(scale * Q @ K^T) (masked -> 0), fp32 inputs converted
    // in-kernel, row sums -> RS
    gemm_k1<<<dim3(NK / BN, NQ / BM, B), 128, SMEM_DB>>>(
        queries, keys, S, NK, D,
        (long long)NQ * D, (long long)NK * D, (long long)NQ * NK,
        mask, (long long)NQ * NK, RS, scale);

    // Join: K3 needs both K1 (stream 0) and K0 (s2).
    cudaStreamWaitEvent(0, eJoin, 0);

    // K3: out = (P @ Vt^T) / rowsum + bias   (fp16 in, fp32 out)
    gemm_h16<<<dim3(O / BN, NQ / BM, B), 128, SMEM_DB>>>(
        S, Vt, out, O, NK,
        (long long)NQ * NK, (long long)O * NK, (long long)NQ * O,
        bias, RS);
}